// round 6
// baseline (speedup 1.0000x reference)
#include <cuda_runtime.h>

#define NN 100000
#define EE 3200000
#define FIN 512
#define HH 16
#define CC 40
#define SCAN_BLOCKS 98   // ceil(100000/1024)

typedef unsigned long long u64;

// ---------------- scratch (device globals; no allocation allowed) ----------
__device__ u64   g_pack[NN];         // (cnt<<40) | fixed24(sum ew)
__device__ float g_dinv[NN];
__device__ int   g_cnt[NN];
__device__ int   g_tmp[NN];
__device__ int   g_off[NN + 1];
__device__ int   g_cur[NN];
__device__ int   g_bsum[128];
__device__ __align__(16) int2  g_csr[EE];          // {row, ew*dinv[row]}
__device__ __align__(16) float g_bufA[NN * HH];
__device__ __align__(16) float g_bufB[NN * HH];

// ---------------- packed f32x2 helpers -------------------------------------
__device__ __forceinline__ void ffma2(u64& d, u64 a, u64 b) {
    asm("fma.rn.f32x2 %0, %1, %2, %0;" : "+l"(d) : "l"(a), "l"(b));
}
__device__ __forceinline__ u64 pack2(float a, float b) {
    u64 r; asm("mov.b64 %0, {%1, %2};" : "=l"(r) : "f"(a), "f"(b)); return r;
}
__device__ __forceinline__ float2 unpack2(u64 v) {
    float2 r; asm("mov.b64 {%0, %1}, %2;" : "=f"(r.x), "=f"(r.y) : "l"(v)); return r;
}

// ---------------- init ------------------------------------------------------
__global__ void k_init() {
    int i = blockIdx.x * blockDim.x + threadIdx.x;
    if (i < NN) g_pack[i] = 0ull;
}

// ---------------- per-edge degree+count: ONE 64-bit atomic per edge --------
// edge_index is int32 (JAX x64 disabled). 2 edges per thread.
__global__ void k_degcnt(const int* __restrict__ ei,
                         const float* __restrict__ ew) {
    int e2 = (blockIdx.x * blockDim.x + threadIdx.x) * 2;
    int2   c = *(const int2*)(ei + EE + e2);
    float2 w = *(const float2*)(ew + e2);
    u64 p0 = (1ull << 40) | (u64)__float2uint_rn(w.x * 16777216.0f);
    u64 p1 = (1ull << 40) | (u64)__float2uint_rn(w.y * 16777216.0f);
    atomicAdd(&g_pack[c.x], p0);
    atomicAdd(&g_pack[c.y], p1);
}

// ---------------- scan pass 1 (+ extract cnt, compute dinv) ----------------
__global__ void k_scan1() {
    __shared__ int sh[256];
    int t = threadIdx.x;
    int base = blockIdx.x * 1024 + t * 4;
    int v[4]; int s = 0;
#pragma unroll
    for (int i = 0; i < 4; i++) {
        int idx = base + i;
        int c = 0;
        if (idx < NN) {
            u64 p = g_pack[idx];
            c = (int)(p >> 40);
            g_cnt[idx] = c;
            float deg = 1.0f + (float)(p & 0xFFFFFFFFFFull) * 5.9604645e-8f;
            g_dinv[idx] = rsqrtf(deg);
        }
        v[i] = c; s += c;
    }
    sh[t] = s; __syncthreads();
    for (int d = 1; d < 256; d <<= 1) {
        int x = (t >= d) ? sh[t - d] : 0;
        __syncthreads();
        sh[t] += x;
        __syncthreads();
    }
    int run = sh[t] - s;
#pragma unroll
    for (int i = 0; i < 4; i++) {
        run += v[i];
        if (base + i < NN) g_tmp[base + i] = run;   // inclusive within block
    }
    if (t == 255) g_bsum[blockIdx.x] = sh[255];
}

// ---------------- scan pass 2: each block sums preceding block totals ------
__global__ void k_scan3() {
    __shared__ int red[8];
    int t = threadIdx.x;
    int v = (t < SCAN_BLOCKS && t < (int)blockIdx.x) ? g_bsum[t] : 0;
#pragma unroll
    for (int d = 16; d; d >>= 1) v += __shfl_xor_sync(0xFFFFFFFFu, v, d);
    if ((t & 31) == 0) red[t >> 5] = v;
    __syncthreads();
    int bo = red[0] + red[1] + red[2] + red[3] +
             red[4] + red[5] + red[6] + red[7];
    int base = blockIdx.x * 1024 + t * 4;
#pragma unroll
    for (int i = 0; i < 4; i++) {
        int idx = base + i;
        if (idx < NN) {
            int o = bo + g_tmp[idx] - g_cnt[idx];  // exclusive offset
            g_off[idx] = o;
            g_cur[idx] = o;
        }
    }
    if (blockIdx.x == 0 && t == 0) g_off[NN] = EE;
}

// ---------------- scatter edges into CSR; norm factored: store ew*dinv[r] --
__global__ void k_scatter(const int* __restrict__ ei,
                          const float* __restrict__ ew) {
    int e2 = (blockIdx.x * blockDim.x + threadIdx.x) * 2;
    int2   r = *(const int2*)(ei + e2);
    int2   c = *(const int2*)(ei + EE + e2);
    float2 w = *(const float2*)(ew + e2);
    float w0 = w.x * g_dinv[r.x];
    float w1 = w.y * g_dinv[r.y];
    int p0 = atomicAdd(&g_cur[c.x], 1);
    g_csr[p0] = make_int2(r.x, __float_as_int(w0));
    int p1 = atomicAdd(&g_cur[c.y], 1);
    g_csr[p1] = make_int2(r.y, __float_as_int(w1));
}

// ---------------- gemm1: bufA = relu(x @ W_first + b), packed f32x2 -------
// 128 threads, 512 rows/block (4 rows/thread strided by 128), K-tiles of 16.
__global__ __launch_bounds__(128) void k_gemm1(const float* __restrict__ x,
                                               const float* __restrict__ W,
                                               const float* __restrict__ b) {
    __shared__ float xs[512 * 17];
    int t = threadIdx.x;
    int rowbase = blockIdx.x * 512;
    u64 acc[4][8];
#pragma unroll
    for (int r = 0; r < 4; r++)
#pragma unroll
        for (int q = 0; q < 8; q++) acc[r][q] = 0ull;

    const float4*     x4 = (const float4*)x;
    const ulonglong2* Wp = (const ulonglong2*)W;   // W row = 64B = 4 loads

    for (int tile = 0; tile < 32; tile++) {
        __syncthreads();
        // stage 512 rows x 16 features: coalesced float4 global loads
#pragma unroll
        for (int i = 0; i < 16; i++) {
            int idx = i * 128 + t;
            int r = idx >> 2, f4 = idx & 3;
            int grow = rowbase + r;
            float4 v = make_float4(0.f, 0.f, 0.f, 0.f);
            if (grow < NN) v = x4[grow * (FIN / 4) + tile * 4 + f4];
            float* dst = &xs[r * 17 + f4 * 4];
            dst[0] = v.x; dst[1] = v.y; dst[2] = v.z; dst[3] = v.w;
        }
        __syncthreads();
#pragma unroll
        for (int f = 0; f < 16; f++) {
            int fg = tile * 16 + f;
            ulonglong2 w0 = __ldg(&Wp[fg * 4 + 0]);
            ulonglong2 w1 = __ldg(&Wp[fg * 4 + 1]);
            ulonglong2 w2 = __ldg(&Wp[fg * 4 + 2]);
            ulonglong2 w3 = __ldg(&Wp[fg * 4 + 3]);
#pragma unroll
            for (int r = 0; r < 4; r++) {
                float xv = xs[(t + r * 128) * 17 + f];
                u64 xp = pack2(xv, xv);
                ffma2(acc[r][0], xp, w0.x); ffma2(acc[r][1], xp, w0.y);
                ffma2(acc[r][2], xp, w1.x); ffma2(acc[r][3], xp, w1.y);
                ffma2(acc[r][4], xp, w2.x); ffma2(acc[r][5], xp, w2.y);
                ffma2(acc[r][6], xp, w3.x); ffma2(acc[r][7], xp, w3.y);
            }
        }
    }
    const float4* b4 = (const float4*)b;
    float4* out4 = (float4*)g_bufA;
#pragma unroll
    for (int r = 0; r < 4; r++) {
        int grow = rowbase + t + r * 128;
        if (grow >= NN) continue;
#pragma unroll
        for (int k4 = 0; k4 < 4; k4++) {
            float4 bb = __ldg(&b4[k4]);
            float2 lo = unpack2(acc[r][k4 * 2 + 0]);
            float2 hi = unpack2(acc[r][k4 * 2 + 1]);
            float4 o;
            o.x = fmaxf(lo.x + bb.x, 0.f);
            o.y = fmaxf(lo.y + bb.y, 0.f);
            o.z = fmaxf(hi.x + bb.z, 0.f);
            o.w = fmaxf(hi.y + bb.w, 0.f);
            out4[grow * 4 + k4] = o;
        }
    }
}

// ---------------- fused conv layer: hout = relu((A @ hin) @ W + b) --------
// ONE WARP PER NODE: lanes (j,k), j in {0,1} handles edges e+j, k = feature.
// 1 csr LDG + 1 gather LDG per 2 edges; uniform loop bounds -> no divergence.
__global__ __launch_bounds__(256) void k_agg(const float* __restrict__ hin,
                                             float* __restrict__ hout,
                                             const float* __restrict__ W,
                                             const float* __restrict__ bias) {
    __shared__ float Ws[256];
    __shared__ float bs[16];
    __shared__ float hb[128];              // 8 warps x 16
    Ws[threadIdx.x] = W[threadIdx.x];
    if (threadIdx.x < 16) bs[threadIdx.x] = bias[threadIdx.x];
    __syncthreads();

    int warp = threadIdx.x >> 5;
    int lane = threadIdx.x & 31;
    int node = blockIdx.x * 8 + warp;      // grid = NN/8 = 12500 exactly
    int j = lane >> 4, k = lane & 15;

    int o0 = g_off[node];
    int o1 = g_off[node + 1];
    float dv = g_dinv[node];
    // factored bracket: sum_e (ew*dinv[r]) h[r] + dinv[c] h[c]
    float acc = (j == 0) ? dv * hin[node * 16 + k] : 0.f;

    for (int e = o0 + j; e < o1; e += 2) {
        int2 pr = __ldg(&g_csr[e]);
        acc += __int_as_float(pr.y) * __ldg(&hin[pr.x * 16 + k]);
    }
    acc += __shfl_xor_sync(0xFFFFFFFFu, acc, 16);
    acc *= dv;                              // multiply dinv[c] once

    // 16x16 transform
    if (j == 0) hb[warp * 16 + k] = acc;
    __syncwarp();
    float o = bs[k];
#pragma unroll
    for (int f = 0; f < 16; f++) o += hb[warp * 16 + f] * Ws[f * 16 + k];
    if (j == 0) hout[node * 16 + k] = fmaxf(o, 0.0f);
}

// ---------------- output: logits (16x40) + log_softmax --------------------
__global__ __launch_bounds__(256) void k_out(const float* __restrict__ Wo,
                                             const float* __restrict__ bo,
                                             float* __restrict__ out) {
    __shared__ float Ws[16 * 40];
    __shared__ float bs[40];
    for (int i = threadIdx.x; i < 640; i += 256) Ws[i] = Wo[i];
    if (threadIdx.x < 40) bs[threadIdx.x] = bo[threadIdx.x];
    __syncthreads();
    int idx = blockIdx.x * blockDim.x + threadIdx.x;
    if (idx >= NN) return;

    const float4* in4 = (const float4*)g_bufA;
    float hx[16];
#pragma unroll
    for (int q = 0; q < 4; q++) {
        float4 v = in4[idx * 4 + q];
        hx[q * 4 + 0] = v.x; hx[q * 4 + 1] = v.y;
        hx[q * 4 + 2] = v.z; hx[q * 4 + 3] = v.w;
    }
    float acc[40];
#pragma unroll
    for (int c = 0; c < 40; c++) acc[c] = bs[c];
#pragma unroll
    for (int f = 0; f < 16; f++) {
        float xv = hx[f];
#pragma unroll
        for (int c = 0; c < 40; c++) acc[c] += xv * Ws[f * 40 + c];
    }
    float m = acc[0];
#pragma unroll
    for (int c = 1; c < 40; c++) m = fmaxf(m, acc[c]);
    float s = 0.f;
#pragma unroll
    for (int c = 0; c < 40; c++) s += __expf(acc[c] - m);
    float lse = m + __logf(s);
#pragma unroll
    for (int c = 0; c < 40; c++) out[idx * 40 + c] = acc[c] - lse;
}

// ---------------- launch ---------------------------------------------------
extern "C" void kernel_launch(void* const* d_in, const int* in_sizes, int n_in,
                              void* d_out, int out_size) {
    const float* x  = (const float*)d_in[0];
    const int*   ei = (const int*)d_in[1];     // int32! (JAX x64 disabled)
    const float* ew = (const float*)d_in[2];
    const float* Wf = (const float*)d_in[3];
    const float* bf = (const float*)d_in[4];
    const float* W1 = (const float*)d_in[5];
    const float* b1 = (const float*)d_in[6];
    const float* W2 = (const float*)d_in[7];
    const float* b2 = (const float*)d_in[8];
    const float* Wo = (const float*)d_in[9];
    const float* bo = (const float*)d_in[10];
    float* out = (float*)d_out;

    float* bufA; float* bufB;
    cudaGetSymbolAddress((void**)&bufA, g_bufA);
    cudaGetSymbolAddress((void**)&bufB, g_bufB);

    k_init   <<<(NN + 255) / 256, 256>>>();
    k_degcnt <<<EE / 512, 256>>>(ei, ew);
    k_scan1  <<<SCAN_BLOCKS, 256>>>();
    k_scan3  <<<SCAN_BLOCKS, 256>>>();
    k_scatter<<<EE / 512, 256>>>(ei, ew);

    k_gemm1  <<<(NN + 511) / 512, 128>>>(x, Wf, bf);

    k_agg    <<<NN / 8, 256>>>(bufA, bufB, W1, b1);
    k_agg    <<<NN / 8, 256>>>(bufB, bufA, W2, b2);

    k_out    <<<(NN + 255) / 256, 256>>>(Wo, bo, out);
}

// round 7
// speedup vs baseline: 1.0740x; 1.0740x over previous
#include <cuda_runtime.h>

#define NN 100000
#define EE 3200000
#define FIN 512
#define HH 16
#define CC 40
#define CAP 128            // bucket capacity per node (deg~Poisson(32), 17-sigma safe)

typedef unsigned long long u64;

// ---------------- scratch (device globals; no allocation allowed) ----------
__device__ int   g_cnt[NN];
__device__ float g_dinv[NN];
__device__ __align__(16) int2  g_csr[NN * CAP];    // {row, ew_bits}, bucketed
__device__ __align__(16) float g_bufA[NN * HH];
__device__ __align__(16) float g_bufB[NN * HH];

// ---------------- packed f32x2 helpers -------------------------------------
__device__ __forceinline__ void ffma2(u64& d, u64 a, u64 b) {
    asm("fma.rn.f32x2 %0, %1, %2, %0;" : "+l"(d) : "l"(a), "l"(b));
}
__device__ __forceinline__ u64 pack2(float a, float b) {
    u64 r; asm("mov.b64 %0, {%1, %2};" : "=l"(r) : "f"(a), "f"(b)); return r;
}
__device__ __forceinline__ float2 unpack2(u64 v) {
    float2 r; asm("mov.b64 {%0, %1}, %2;" : "=f"(r.x), "=f"(r.y) : "l"(v)); return r;
}

// ---------------- init: zero counts ----------------------------------------
__global__ void k_init() {
    int i = blockIdx.x * blockDim.x + threadIdx.x;
    if (i < NN) g_cnt[i] = 0;
}

// ---------------- scatter: bucketed CSR, raw ew, ONE atomic per edge -------
// edge_index is int32 (JAX x64 disabled). 2 edges per thread, vectorized.
__global__ void k_scatter(const int* __restrict__ ei,
                          const float* __restrict__ ew) {
    int e2 = (blockIdx.x * blockDim.x + threadIdx.x) * 2;
    int2   r = *(const int2*)(ei + e2);
    int2   c = *(const int2*)(ei + EE + e2);
    float2 w = *(const float2*)(ew + e2);
    int s0 = atomicAdd(&g_cnt[c.x], 1);
    g_csr[(c.x << 7) + s0] = make_int2(r.x, __float_as_int(w.x));
    int s1 = atomicAdd(&g_cnt[c.y], 1);
    g_csr[(c.y << 7) + s1] = make_int2(r.y, __float_as_int(w.y));
}

// ---------------- weighted degree -> dinv (sequential sweep, no atomics) ---
// half-warp (16 lanes) per node: coalesced 128B reads of the bucket.
__global__ __launch_bounds__(256) void k_deg() {
    int tid  = blockIdx.x * 256 + threadIdx.x;
    int node = tid >> 4;
    int l    = tid & 15;
    int cnt  = g_cnt[node];
    int base = node << 7;
    float s = 0.f;
    for (int i = l; i < cnt; i += 16)
        s += __int_as_float(g_csr[base + i].y);
#pragma unroll
    for (int d = 8; d; d >>= 1) s += __shfl_xor_sync(0xFFFFFFFFu, s, d, 16);
    if (l == 0) g_dinv[node] = rsqrtf(1.0f + s);   // +1 = self loop
}

// ---------------- gemm1: bufA = dinv * relu(x @ W_first + b) ---------------
// 128 threads, 256 rows/block (2 rows/thread), feature tiles of 32. (R4 form)
__global__ __launch_bounds__(128) void k_gemm1(const float* __restrict__ x,
                                               const float* __restrict__ W,
                                               const float* __restrict__ b) {
    __shared__ float xs[256 * 33];
    int t = threadIdx.x;
    int rowbase = blockIdx.x * 256;
    u64 acc0[8], acc1[8];
#pragma unroll
    for (int k = 0; k < 8; k++) { acc0[k] = 0ull; acc1[k] = 0ull; }

    const float4*     x4 = (const float4*)x;
    const ulonglong2* Wp = (const ulonglong2*)W;

    for (int tile = 0; tile < 16; tile++) {
        __syncthreads();
#pragma unroll
        for (int i = 0; i < 16; i++) {
            int idx = i * 128 + t;
            int r = idx >> 3, f4 = idx & 7;
            int grow = rowbase + r;
            float4 v = make_float4(0.f, 0.f, 0.f, 0.f);
            if (grow < NN) v = x4[grow * (FIN / 4) + tile * 8 + f4];
            float* dst = &xs[r * 33 + f4 * 4];
            dst[0] = v.x; dst[1] = v.y; dst[2] = v.z; dst[3] = v.w;
        }
        __syncthreads();
#pragma unroll 8
        for (int f = 0; f < 32; f++) {
            float xv0 = xs[t * 33 + f];
            float xv1 = xs[(t + 128) * 33 + f];
            u64 xp0 = pack2(xv0, xv0);
            u64 xp1 = pack2(xv1, xv1);
            int fg = tile * 32 + f;
#pragma unroll
            for (int q = 0; q < 4; q++) {
                ulonglong2 wp = __ldg(&Wp[fg * 4 + q]);
                ffma2(acc0[q * 2 + 0], xp0, wp.x);
                ffma2(acc0[q * 2 + 1], xp0, wp.y);
                ffma2(acc1[q * 2 + 0], xp1, wp.x);
                ffma2(acc1[q * 2 + 1], xp1, wp.y);
            }
        }
    }
    const float4* b4 = (const float4*)b;
    float4* out4 = (float4*)g_bufA;
    int r0 = rowbase + t;
    int r1 = rowbase + t + 128;
    float dv0 = (r0 < NN) ? g_dinv[r0] : 0.f;
    float dv1 = (r1 < NN) ? g_dinv[r1] : 0.f;
#pragma unroll
    for (int k4 = 0; k4 < 4; k4++) {
        float4 bb = __ldg(&b4[k4]);
        float2 a0 = unpack2(acc0[k4 * 2 + 0]);
        float2 a1 = unpack2(acc0[k4 * 2 + 1]);
        float2 c0 = unpack2(acc1[k4 * 2 + 0]);
        float2 c1 = unpack2(acc1[k4 * 2 + 1]);
        if (r0 < NN) {
            float4 o;
            o.x = fmaxf(a0.x + bb.x, 0.f) * dv0;
            o.y = fmaxf(a0.y + bb.y, 0.f) * dv0;
            o.z = fmaxf(a1.x + bb.z, 0.f) * dv0;
            o.w = fmaxf(a1.y + bb.w, 0.f) * dv0;
            out4[r0 * 4 + k4] = o;
        }
        if (r1 < NN) {
            float4 o;
            o.x = fmaxf(c0.x + bb.x, 0.f) * dv1;
            o.y = fmaxf(c0.y + bb.y, 0.f) * dv1;
            o.z = fmaxf(c1.x + bb.z, 0.f) * dv1;
            o.w = fmaxf(c1.y + bb.w, 0.f) * dv1;
            out4[r1 * 4 + k4] = o;
        }
    }
}

// ---------------- fused conv: hout = [dinv*] relu((A @ hin) @ W + b) -------
// hin is pre-scaled by dinv (h' = dinv*h), so per-edge work uses RAW ew:
//   agg_c = dinv_c * ( sum_e ew_e * h'_r  +  h'_c )
// half-warp per node; 16-edge chunks read as 8x int4 (2 edges per LDG.128).
__global__ __launch_bounds__(256) void k_agg(const float* __restrict__ hin,
                                             float* __restrict__ hout,
                                             const float* __restrict__ W,
                                             const float* __restrict__ bias,
                                             int premul) {
    __shared__ float Ws[256];
    __shared__ float bs[16];
    __shared__ float hb[256];
    Ws[threadIdx.x] = W[threadIdx.x];
    if (threadIdx.x < 16) bs[threadIdx.x] = bias[threadIdx.x];
    __syncthreads();

    int tid = blockIdx.x * 256 + threadIdx.x;     // grid = NN*16/256 exactly
    int node = tid >> 4;
    int k = tid & 15;

    int cnt  = g_cnt[node];
    int base = node << 7;
    float acc = hin[node * 16 + k];               // self loop (already scaled)

    const int4* csr4 = (const int4*)g_csr;        // 2 edges per int4
    for (int e = 0; e < cnt; e += 16) {
#pragma unroll
        for (int j = 0; j < 8; j++) {
            int idx = e + j * 2;
            if (idx < cnt) {
                int4 pq = __ldg(&csr4[(base + idx) >> 1]);
                acc += __int_as_float(pq.y) * __ldg(&hin[pq.x * 16 + k]);
                if (idx + 1 < cnt)
                    acc += __int_as_float(pq.w) * __ldg(&hin[pq.z * 16 + k]);
            }
        }
    }
    float dv = g_dinv[node];
    acc *= dv;

    // 16x16 transform: exchange aggregated feats within the half-warp
    hb[threadIdx.x] = acc;
    __syncwarp();
    int hbase = threadIdx.x & ~15;
    float o = bs[k];
#pragma unroll
    for (int f = 0; f < 16; f++) o += hb[hbase + f] * Ws[f * 16 + k];
    float res = fmaxf(o, 0.0f);
    if (premul) res *= dv;                        // pre-scale for next layer
    hout[node * 16 + k] = res;
}

// ---------------- output: logits (16x40) + log_softmax --------------------
__global__ __launch_bounds__(256) void k_out(const float* __restrict__ Wo,
                                             const float* __restrict__ bo,
                                             float* __restrict__ out) {
    __shared__ float Ws[16 * 40];
    __shared__ float bs[40];
    for (int i = threadIdx.x; i < 640; i += 256) Ws[i] = Wo[i];
    if (threadIdx.x < 40) bs[threadIdx.x] = bo[threadIdx.x];
    __syncthreads();
    int idx = blockIdx.x * blockDim.x + threadIdx.x;
    if (idx >= NN) return;

    const float4* in4 = (const float4*)g_bufA;
    float hx[16];
#pragma unroll
    for (int q = 0; q < 4; q++) {
        float4 v = in4[idx * 4 + q];
        hx[q * 4 + 0] = v.x; hx[q * 4 + 1] = v.y;
        hx[q * 4 + 2] = v.z; hx[q * 4 + 3] = v.w;
    }
    float acc[40];
#pragma unroll
    for (int c = 0; c < 40; c++) acc[c] = bs[c];
#pragma unroll
    for (int f = 0; f < 16; f++) {
        float xv = hx[f];
#pragma unroll
        for (int c = 0; c < 40; c++) acc[c] += xv * Ws[f * 40 + c];
    }
    float m = acc[0];
#pragma unroll
    for (int c = 1; c < 40; c++) m = fmaxf(m, acc[c]);
    float s = 0.f;
#pragma unroll
    for (int c = 0; c < 40; c++) s += __expf(acc[c] - m);
    float lse = m + __logf(s);
#pragma unroll
    for (int c = 0; c < 40; c++) out[idx * 40 + c] = acc[c] - lse;
}

// ---------------- launch ---------------------------------------------------
extern "C" void kernel_launch(void* const* d_in, const int* in_sizes, int n_in,
                              void* d_out, int out_size) {
    const float* x  = (const float*)d_in[0];
    const int*   ei = (const int*)d_in[1];     // int32! (JAX x64 disabled)
    const float* ew = (const float*)d_in[2];
    const float* Wf = (const float*)d_in[3];
    const float* bf = (const float*)d_in[4];
    const float* W1 = (const float*)d_in[5];
    const float* b1 = (const float*)d_in[6];
    const float* W2 = (const float*)d_in[7];
    const float* b2 = (const float*)d_in[8];
    const float* Wo = (const float*)d_in[9];
    const float* bo = (const float*)d_in[10];
    float* out = (float*)d_out;

    float* bufA; float* bufB;
    cudaGetSymbolAddress((void**)&bufA, g_bufA);
    cudaGetSymbolAddress((void**)&bufB, g_bufB);

    k_init   <<<(NN + 255) / 256, 256>>>();
    k_scatter<<<EE / 512, 256>>>(ei, ew);
    k_deg    <<<NN / 16, 256>>>();

    k_gemm1  <<<(NN + 255) / 256, 128>>>(x, Wf, bf);

    k_agg    <<<NN * 16 / 256, 256>>>(bufA, bufB, W1, b1, 1);
    k_agg    <<<NN * 16 / 256, 256>>>(bufB, bufA, W2, b2, 0);

    k_out    <<<(NN + 255) / 256, 256>>>(Wo, bo, out);
}

// round 10
// speedup vs baseline: 1.1382x; 1.0598x over previous
#include <cuda_runtime.h>

#define NN 100000
#define EE 3200000
#define FIN 512
#define HH 16
#define CC 40
#define CAP 128            // bucket capacity per node (deg~Poisson(32), 17-sigma safe)
#define KCH 4              // gemm1 K-split chunks
#define RB  196            // row-blocks in gemm1 = ceil(NN/512)

typedef unsigned long long u64;

// ---------------- scratch (device globals; no allocation allowed) ----------
__device__ int   g_cnt[NN];
__device__ float g_dinv[NN];
__device__ __align__(16) int2  g_csr[NN * CAP];     // {row, ew_bits}, bucketed
__device__ __align__(16) float g_part[KCH * NN * HH];
__device__ __align__(16) float g_bufA[NN * HH];
__device__ __align__(16) float g_bufB[NN * HH];

// ---------------- packed f32x2 helpers -------------------------------------
__device__ __forceinline__ void ffma2(u64& d, u64 a, u64 b) {
    asm("fma.rn.f32x2 %0, %1, %2, %0;" : "+l"(d) : "l"(a), "l"(b));
}
__device__ __forceinline__ u64 pack2(float a, float b) {
    u64 r; asm("mov.b64 %0, {%1, %2};" : "=l"(r) : "f"(a), "f"(b)); return r;
}
__device__ __forceinline__ float2 unpack2(u64 v) {
    float2 r; asm("mov.b64 {%0, %1}, %2;" : "=f"(r.x), "=f"(r.y) : "l"(v)); return r;
}

// ---------------- init: zero counts ----------------------------------------
__global__ void k_init() {
    int i = blockIdx.x * blockDim.x + threadIdx.x;
    if (i < NN) g_cnt[i] = 0;
}

// ---------------- scatter: bucketed CSR, raw ew, ONE atomic per edge -------
// edge_index is int32 (JAX x64 disabled). 2 edges per thread, vectorized.
__global__ void k_scatter(const int* __restrict__ ei,
                          const float* __restrict__ ew) {
    int e2 = (blockIdx.x * blockDim.x + threadIdx.x) * 2;
    int2   r = *(const int2*)(ei + e2);
    int2   c = *(const int2*)(ei + EE + e2);
    float2 w = *(const float2*)(ew + e2);
    int s0 = atomicAdd(&g_cnt[c.x], 1);
    g_csr[(c.x << 7) + s0] = make_int2(r.x, __float_as_int(w.x));
    int s1 = atomicAdd(&g_cnt[c.y], 1);
    g_csr[(c.y << 7) + s1] = make_int2(r.y, __float_as_int(w.y));
}

// ---------------- weighted degree -> dinv (sequential sweep, no atomics) ---
__global__ __launch_bounds__(256) void k_deg() {
    int tid  = blockIdx.x * 256 + threadIdx.x;
    int node = tid >> 4;
    int l    = tid & 15;
    int cnt  = g_cnt[node];
    int base = node << 7;
    float s = 0.f;
    for (int i = l; i < cnt; i += 16)
        s += __int_as_float(g_csr[base + i].y);
#pragma unroll
    for (int d = 8; d; d >>= 1) s += __shfl_xor_sync(0xFFFFFFFFu, s, d, 16);
    if (l == 0) g_dinv[node] = rsqrtf(1.0f + s);   // +1 = self loop
}

// ---------------- gemm1 split-K: part[chunk] = x[:,chunk] @ W[chunk,:] -----
// 1-D grid of RB*KCH blocks; 256 threads; 512 rows/block (2 rows/thread).
__global__ __launch_bounds__(256) void k_gemm1(const float* __restrict__ x,
                                               const float* __restrict__ W) {
    __shared__ float xs[512 * 17];
    int t = threadIdx.x;
    int rowblk = blockIdx.x % RB;
    int chunk  = blockIdx.x / RB;                  // K-chunk of 128 feats
    int rowbase = rowblk * 512;
    u64 acc0[8], acc1[8];
#pragma unroll
    for (int k = 0; k < 8; k++) { acc0[k] = 0ull; acc1[k] = 0ull; }

    const float4*     x4 = (const float4*)x;
    const ulonglong2* Wp = (const ulonglong2*)W;

    for (int tile = 0; tile < 8; tile++) {         // 8 x 16 = 128 feats
        int fbase = chunk * 32 + tile * 4;         // in float4 units
        __syncthreads();
        // stage 512 rows x 16 feats: 8 coalesced float4 loads per thread
#pragma unroll
        for (int i = 0; i < 8; i++) {
            int idx = i * 256 + t;
            int r = idx >> 2, f4 = idx & 3;
            int grow = rowbase + r;
            float4 v = make_float4(0.f, 0.f, 0.f, 0.f);
            if (grow < NN) v = x4[grow * (FIN / 4) + fbase + f4];
            float* dst = &xs[r * 17 + f4 * 4];
            dst[0] = v.x; dst[1] = v.y; dst[2] = v.z; dst[3] = v.w;
        }
        __syncthreads();
#pragma unroll
        for (int f = 0; f < 16; f++) {
            int fg = chunk * 128 + tile * 16 + f;
            ulonglong2 w0 = __ldg(&Wp[fg * 4 + 0]);
            ulonglong2 w1 = __ldg(&Wp[fg * 4 + 1]);
            ulonglong2 w2 = __ldg(&Wp[fg * 4 + 2]);
            ulonglong2 w3 = __ldg(&Wp[fg * 4 + 3]);
            float xv0 = xs[t * 17 + f];
            float xv1 = xs[(t + 256) * 17 + f];
            u64 xp0 = pack2(xv0, xv0);
            u64 xp1 = pack2(xv1, xv1);
            ffma2(acc0[0], xp0, w0.x); ffma2(acc0[1], xp0, w0.y);
            ffma2(acc0[2], xp0, w1.x); ffma2(acc0[3], xp0, w1.y);
            ffma2(acc0[4], xp0, w2.x); ffma2(acc0[5], xp0, w2.y);
            ffma2(acc0[6], xp0, w3.x); ffma2(acc0[7], xp0, w3.y);
            ffma2(acc1[0], xp1, w0.x); ffma2(acc1[1], xp1, w0.y);
            ffma2(acc1[2], xp1, w1.x); ffma2(acc1[3], xp1, w1.y);
            ffma2(acc1[4], xp1, w2.x); ffma2(acc1[5], xp1, w2.y);
            ffma2(acc1[6], xp1, w3.x); ffma2(acc1[7], xp1, w3.y);
        }
    }
    float4* out4 = (float4*)(g_part + chunk * NN * HH);
    int r0 = rowbase + t;
    int r1 = rowbase + t + 256;
#pragma unroll
    for (int k4 = 0; k4 < 4; k4++) {
        if (r0 < NN) {
            float2 lo = unpack2(acc0[k4 * 2 + 0]);
            float2 hi = unpack2(acc0[k4 * 2 + 1]);
            out4[r0 * 4 + k4] = make_float4(lo.x, lo.y, hi.x, hi.y);
        }
        if (r1 < NN) {
            float2 lo = unpack2(acc1[k4 * 2 + 0]);
            float2 hi = unpack2(acc1[k4 * 2 + 1]);
            out4[r1 * 4 + k4] = make_float4(lo.x, lo.y, hi.x, hi.y);
        }
    }
}

// ---------------- gemm1 reduce: bufA = dinv * relu(sum parts + b) ----------
__global__ __launch_bounds__(256) void k_gfin(const float* __restrict__ b) {
    int idx = blockIdx.x * 256 + threadIdx.x;      // float4 index
    if (idx >= NN * 4) return;
    const float4* p = (const float4*)g_part;
    float4 p0 = p[idx];
    float4 p1 = p[idx + NN * 4];
    float4 p2 = p[idx + NN * 8];
    float4 p3 = p[idx + NN * 12];
    int row = idx >> 2, k4 = idx & 3;
    float4 bb = __ldg(&((const float4*)b)[k4]);
    float dv = g_dinv[row];
    float4 o;
    o.x = fmaxf(p0.x + p1.x + p2.x + p3.x + bb.x, 0.f) * dv;
    o.y = fmaxf(p0.y + p1.y + p2.y + p3.y + bb.y, 0.f) * dv;
    o.z = fmaxf(p0.z + p1.z + p2.z + p3.z + bb.z, 0.f) * dv;
    o.w = fmaxf(p0.w + p1.w + p2.w + p3.w + bb.w, 0.f) * dv;
    ((float4*)g_bufA)[idx] = o;
}

// ---------------- fused conv: hout = [dinv*] relu((A @ hin) @ W + b) -------
// hin is pre-scaled by dinv (h' = dinv*h):
//   agg_c = dinv_c * ( sum_e ew_e * h'_r  +  h'_c )
// half-warp per node; 16-edge chunks read as 8x int4 (2 edges per LDG.128).
__global__ __launch_bounds__(256) void k_agg(const float* __restrict__ hin,
                                             float* __restrict__ hout,
                                             const float* __restrict__ W,
                                             const float* __restrict__ bias,
                                             int premul) {
    __shared__ float Ws[256];
    __shared__ float bs[16];
    __shared__ float hb[256];
    Ws[threadIdx.x] = W[threadIdx.x];
    if (threadIdx.x < 16) bs[threadIdx.x] = bias[threadIdx.x];
    __syncthreads();

    int tid = blockIdx.x * 256 + threadIdx.x;     // grid = NN*16/256 exactly
    int node = tid >> 4;
    int k = tid & 15;

    int cnt  = g_cnt[node];
    int base = node << 7;
    float acc = hin[node * 16 + k];               // self loop (already scaled)

    const int4* csr4 = (const int4*)g_csr;        // 2 edges per int4
    for (int e = 0; e < cnt; e += 16) {
#pragma unroll
        for (int j = 0; j < 8; j++) {
            int idx = e + j * 2;
            if (idx < cnt) {
                int4 pq = __ldg(&csr4[(base + idx) >> 1]);
                acc += __int_as_float(pq.y) * __ldg(&hin[pq.x * 16 + k]);
                if (idx + 1 < cnt)
                    acc += __int_as_float(pq.w) * __ldg(&hin[pq.z * 16 + k]);
            }
        }
    }
    float dv = g_dinv[node];
    acc *= dv;

    // 16x16 transform: exchange aggregated feats within the half-warp
    hb[threadIdx.x] = acc;
    __syncwarp();
    int hbase = threadIdx.x & ~15;
    float o = bs[k];
#pragma unroll
    for (int f = 0; f < 16; f++) o += hb[hbase + f] * Ws[f * 16 + k];
    float res = fmaxf(o, 0.0f);
    if (premul) res *= dv;                        // pre-scale for next layer
    hout[node * 16 + k] = res;
}

// ---------------- output: logits (16x40) + log_softmax --------------------
__global__ __launch_bounds__(256) void k_out(const float* __restrict__ Wo,
                                             const float* __restrict__ bo,
                                             float* __restrict__ out) {
    __shared__ float Ws[16 * 40];
    __shared__ float bs[40];
    for (int i = threadIdx.x; i < 640; i += 256) Ws[i] = Wo[i];
    if (threadIdx.x < 40) bs[threadIdx.x] = bo[threadIdx.x];
    __syncthreads();
    int idx = blockIdx.x * blockDim.x + threadIdx.x;
    if (idx >= NN) return;

    const float4* in4 = (const float4*)g_bufA;
    float hx[16];
#pragma unroll
    for (int q = 0; q < 4; q++) {
        float4 v = in4[idx * 4 + q];
        hx[q * 4 + 0] = v.x; hx[q * 4 + 1] = v.y;
        hx[q * 4 + 2] = v.z; hx[q * 4 + 3] = v.w;
    }
    float acc[40];
#pragma unroll
    for (int c = 0; c < 40; c++) acc[c] = bs[c];
#pragma unroll
    for (int f = 0; f < 16; f++) {
        float xv = hx[f];
#pragma unroll
        for (int c = 0; c < 40; c++) acc[c] += xv * Ws[f * 40 + c];
    }
    float m = acc[0];
#pragma unroll
    for (int c = 1; c < 40; c++) m = fmaxf(m, acc[c]);
    float s = 0.f;
#pragma unroll
    for (int c = 0; c < 40; c++) s += __expf(acc[c] - m);
    float lse = m + __logf(s);
#pragma unroll
    for (int c = 0; c < 40; c++) out[idx * 40 + c] = acc[c] - lse;
}

// ---------------- launch ---------------------------------------------------
extern "C" void kernel_launch(void* const* d_in, const int* in_sizes, int n_in,
                              void* d_out, int out_size) {
    const float* x  = (const float*)d_in[0];
    const int*   ei = (const int*)d_in[1];     // int32! (JAX x64 disabled)
    const float* ew = (const float*)d_in[2];
    const float* Wf = (const float*)d_in[3];
    const float* bf = (const float*)d_in[4];
    const float* W1 = (const float*)d_in[5];
    const float* b1 = (const float*)d_in[6];
    const float* W2 = (const float*)d_in[7];
    const float* b2 = (const float*)d_in[8];
    const float* Wo = (const float*)d_in[9];
    const float* bo = (const float*)d_in[10];
    float* out = (float*)d_out;

    float* bufA; float* bufB;
    cudaGetSymbolAddress((void**)&bufA, g_bufA);
    cudaGetSymbolAddress((void**)&bufB, g_bufB);

    k_init   <<<(NN + 255) / 256, 256>>>();
    k_scatter<<<EE / 512, 256>>>(ei, ew);
    k_deg    <<<NN / 16, 256>>>();

    k_gemm1  <<<RB * KCH, 256>>>(x, Wf);
    k_gfin   <<<(NN * 4 + 255) / 256, 256>>>(bf);

    k_agg    <<<NN * 16 / 256, 256>>>(bufA, bufB, W1, b1, 1);
    k_agg    <<<NN * 16 / 256, 256>>>(bufB, bufA, W2, b2, 0);

    k_out    <<<(NN + 255) / 256, 256>>>(Wo, bo, out);
}

// round 12
// speedup vs baseline: 1.1816x; 1.0381x over previous
#include <cuda_runtime.h>

#define NN 100000
#define EE 3200000
#define FIN 512
#define HH 16
#define CC 40
#define CAP 128            // bucket capacity per node (deg~Poisson(32), 17-sigma safe)
#define KCH 4              // gemm1 K-split chunks
#define RB  391            // row-blocks in gemm1 = ceil(NN/256)

typedef unsigned long long u64;

// ---------------- scratch (device globals; no allocation allowed) ----------
__device__ int   g_cnt[NN];
__device__ float g_dinv[NN];
__device__ __align__(16) int2  g_csr[NN * CAP];     // {row, ew_bits}, bucketed
__device__ __align__(16) float g_part[KCH * NN * HH];
__device__ __align__(16) float g_bufA[NN * HH];
__device__ __align__(16) float g_bufB[NN * HH];

// ---------------- packed f32x2 helpers -------------------------------------
__device__ __forceinline__ void ffma2(u64& d, u64 a, u64 b) {
    asm("fma.rn.f32x2 %0, %1, %2, %0;" : "+l"(d) : "l"(a), "l"(b));
}
__device__ __forceinline__ u64 pack2(float a, float b) {
    u64 r; asm("mov.b64 %0, {%1, %2};" : "=l"(r) : "f"(a), "f"(b)); return r;
}
__device__ __forceinline__ float2 unpack2(u64 v) {
    float2 r; asm("mov.b64 {%0, %1}, %2;" : "=f"(r.x), "=f"(r.y) : "l"(v)); return r;
}

// ---------------- init: zero counts ----------------------------------------
__global__ void k_init() {
    int i = blockIdx.x * blockDim.x + threadIdx.x;
    if (i < NN) g_cnt[i] = 0;
}

// ---------------- scatter: bucketed CSR, raw ew, ONE atomic per edge -------
// edge_index is int32 (JAX x64 disabled). 2 edges per thread, vectorized.
__global__ void k_scatter(const int* __restrict__ ei,
                          const float* __restrict__ ew) {
    int e2 = (blockIdx.x * blockDim.x + threadIdx.x) * 2;
    int2   r = *(const int2*)(ei + e2);
    int2   c = *(const int2*)(ei + EE + e2);
    float2 w = *(const float2*)(ew + e2);
    int s0 = atomicAdd(&g_cnt[c.x], 1);
    g_csr[(c.x << 7) + s0] = make_int2(r.x, __float_as_int(w.x));
    int s1 = atomicAdd(&g_cnt[c.y], 1);
    g_csr[(c.y << 7) + s1] = make_int2(r.y, __float_as_int(w.y));
}

// ---------------- weighted degree -> dinv (sequential sweep, no atomics) ---
__global__ __launch_bounds__(256) void k_deg() {
    int tid  = blockIdx.x * 256 + threadIdx.x;
    int node = tid >> 4;
    int l    = tid & 15;
    int cnt  = g_cnt[node];
    int base = node << 7;
    float s = 0.f;
    for (int i = l; i < cnt; i += 16)
        s += __int_as_float(g_csr[base + i].y);
#pragma unroll
    for (int d = 8; d; d >>= 1) s += __shfl_xor_sync(0xFFFFFFFFu, s, d, 16);
    if (l == 0) g_dinv[node] = rsqrtf(1.0f + s);   // +1 = self loop
}

// ---------------- gemm1 split-K, k-split threads ---------------------------
// 256 threads = 128 row-slots x 2 k-halves; each thread: 2 rows x 8 outputs.
// 8 u64 accumulators (16 regs) -> high occupancy. Block covers 256 rows.
__global__ __launch_bounds__(256) void k_gemm1(const float* __restrict__ x,
                                               const float* __restrict__ W) {
    __shared__ float xs[256 * 17];
    int t = threadIdx.x;
    int rowblk = blockIdx.x % RB;
    int chunk  = blockIdx.x / RB;                  // K-chunk of 128 feats
    int rowbase = rowblk * 256;
    int khalf = t & 1;                             // 0: k 0-7, 1: k 8-15
    int slot  = t >> 1;                            // 0..127
    u64 acc0[4], acc1[4];
#pragma unroll
    for (int q = 0; q < 4; q++) { acc0[q] = 0ull; acc1[q] = 0ull; }

    const float4*     x4 = (const float4*)x;
    const ulonglong2* Wp = (const ulonglong2*)W;

    for (int tile = 0; tile < 8; tile++) {         // 8 x 16 = 128 feats
        int fbase = chunk * 32 + tile * 4;         // in float4 units
        __syncthreads();
        // stage 256 rows x 16 feats: 4 coalesced float4 loads per thread
#pragma unroll
        for (int i = 0; i < 4; i++) {
            int idx = i * 256 + t;
            int r = idx >> 2, f4 = idx & 3;
            int grow = rowbase + r;
            float4 v = make_float4(0.f, 0.f, 0.f, 0.f);
            if (grow < NN) v = x4[grow * (FIN / 4) + fbase + f4];
            float* dst = &xs[r * 17 + f4 * 4];
            dst[0] = v.x; dst[1] = v.y; dst[2] = v.z; dst[3] = v.w;
        }
        __syncthreads();
#pragma unroll
        for (int f = 0; f < 16; f++) {
            int fg = chunk * 128 + tile * 16 + f;
            const ulonglong2* wrow = Wp + fg * 4 + khalf * 2;
            ulonglong2 wa = __ldg(wrow);
            ulonglong2 wb = __ldg(wrow + 1);
            float xv0 = xs[slot * 17 + f];          // row slot
            float xv1 = xs[(slot + 128) * 17 + f];  // row slot+128
            u64 xp0 = pack2(xv0, xv0);
            u64 xp1 = pack2(xv1, xv1);
            ffma2(acc0[0], xp0, wa.x); ffma2(acc0[1], xp0, wa.y);
            ffma2(acc0[2], xp0, wb.x); ffma2(acc0[3], xp0, wb.y);
            ffma2(acc1[0], xp1, wa.x); ffma2(acc1[1], xp1, wa.y);
            ffma2(acc1[2], xp1, wb.x); ffma2(acc1[3], xp1, wb.y);
        }
    }
    float4* out4 = (float4*)(g_part + chunk * NN * HH);
    int r0 = rowbase + slot;
    int r1 = rowbase + slot + 128;
    if (r0 < NN) {
        float2 a = unpack2(acc0[0]); float2 b = unpack2(acc0[1]);
        float2 c = unpack2(acc0[2]); float2 d = unpack2(acc0[3]);
        out4[r0 * 4 + khalf * 2 + 0] = make_float4(a.x, a.y, b.x, b.y);
        out4[r0 * 4 + khalf * 2 + 1] = make_float4(c.x, c.y, d.x, d.y);
    }
    if (r1 < NN) {
        float2 a = unpack2(acc1[0]); float2 b = unpack2(acc1[1]);
        float2 c = unpack2(acc1[2]); float2 d = unpack2(acc1[3]);
        out4[r1 * 4 + khalf * 2 + 0] = make_float4(a.x, a.y, b.x, b.y);
        out4[r1 * 4 + khalf * 2 + 1] = make_float4(c.x, c.y, d.x, d.y);
    }
}

// ---------------- gemm1 reduce: bufA = dinv * relu(sum parts + b) ----------
__global__ __launch_bounds__(256) void k_gfin(const float* __restrict__ b) {
    int idx = blockIdx.x * 256 + threadIdx.x;      // float4 index
    if (idx >= NN * 4) return;
    const float4* p = (const float4*)g_part;
    float4 p0 = p[idx];
    float4 p1 = p[idx + NN * 4];
    float4 p2 = p[idx + NN * 8];
    float4 p3 = p[idx + NN * 12];
    int row = idx >> 2, k4 = idx & 3;
    float4 bb = __ldg(&((const float4*)b)[k4]);
    float dv = g_dinv[row];
    float4 o;
    o.x = fmaxf(p0.x + p1.x + p2.x + p3.x + bb.x, 0.f) * dv;
    o.y = fmaxf(p0.y + p1.y + p2.y + p3.y + bb.y, 0.f) * dv;
    o.z = fmaxf(p0.z + p1.z + p2.z + p3.z + bb.z, 0.f) * dv;
    o.w = fmaxf(p0.w + p1.w + p2.w + p3.w + bb.w, 0.f) * dv;
    ((float4*)g_bufA)[idx] = o;
}

// ---------------- fused conv: hout = [dinv*] relu((A @ hin) @ W + b) -------
// hin is pre-scaled by dinv (h' = dinv*h):
//   agg_c = dinv_c * ( sum_e ew_e * h'_r  +  h'_c )
// half-warp per node; 16-edge chunks read as 8x int4 (2 edges per LDG.128).
__global__ __launch_bounds__(256) void k_agg(const float* __restrict__ hin,
                                             float* __restrict__ hout,
                                             const float* __restrict__ W,
                                             const float* __restrict__ bias,
                                             int premul) {
    __shared__ float Ws[256];
    __shared__ float bs[16];
    __shared__ float hb[256];
    Ws[threadIdx.x] = W[threadIdx.x];
    if (threadIdx.x < 16) bs[threadIdx.x] = bias[threadIdx.x];
    __syncthreads();

    int tid = blockIdx.x * 256 + threadIdx.x;     // grid = NN*16/256 exactly
    int node = tid >> 4;
    int k = tid & 15;

    int cnt  = g_cnt[node];
    int base = node << 7;
    float acc = hin[node * 16 + k];               // self loop (already scaled)

    const int4* csr4 = (const int4*)g_csr;        // 2 edges per int4
    for (int e = 0; e < cnt; e += 16) {
#pragma unroll
        for (int j = 0; j < 8; j++) {
            int idx = e + j * 2;
            if (idx < cnt) {
                int4 pq = __ldg(&csr4[(base + idx) >> 1]);
                acc += __int_as_float(pq.y) * __ldg(&hin[pq.x * 16 + k]);
                if (idx + 1 < cnt)
                    acc += __int_as_float(pq.w) * __ldg(&hin[pq.z * 16 + k]);
            }
        }
    }
    float dv = g_dinv[node];
    acc *= dv;

    // 16x16 transform: exchange aggregated feats within the half-warp
    hb[threadIdx.x] = acc;
    __syncwarp();
    int hbase = threadIdx.x & ~15;
    float o = bs[k];
#pragma unroll
    for (int f = 0; f < 16; f++) o += hb[hbase + f] * Ws[f * 16 + k];
    float res = fmaxf(o, 0.0f);
    if (premul) res *= dv;                        // pre-scale for next layer
    hout[node * 16 + k] = res;
}

// ---------------- output: logits (16x40) + log_softmax --------------------
__global__ __launch_bounds__(256) void k_out(const float* __restrict__ Wo,
                                             const float* __restrict__ bo,
                                             float* __restrict__ out) {
    __shared__ float Ws[16 * 40];
    __shared__ float bs[40];
    for (int i = threadIdx.x; i < 640; i += 256) Ws[i] = Wo[i];
    if (threadIdx.x < 40) bs[threadIdx.x] = bo[threadIdx.x];
    __syncthreads();
    int idx = blockIdx.x * blockDim.x + threadIdx.x;
    if (idx >= NN) return;

    const float4* in4 = (const float4*)g_bufA;
    float hx[16];
#pragma unroll
    for (int q = 0; q < 4; q++) {
        float4 v = in4[idx * 4 + q];
        hx[q * 4 + 0] = v.x; hx[q * 4 + 1] = v.y;
        hx[q * 4 + 2] = v.z; hx[q * 4 + 3] = v.w;
    }
    float acc[40];
#pragma unroll
    for (int c = 0; c < 40; c++) acc[c] = bs[c];
#pragma unroll
    for (int f = 0; f < 16; f++) {
        float xv = hx[f];
#pragma unroll
        for (int c = 0; c < 40; c++) acc[c] += xv * Ws[f * 40 + c];
    }
    float m = acc[0];
#pragma unroll
    for (int c = 1; c < 40; c++) m = fmaxf(m, acc[c]);
    float s = 0.f;
#pragma unroll
    for (int c = 0; c < 40; c++) s += __expf(acc[c] - m);
    float lse = m + __logf(s);
#pragma unroll
    for (int c = 0; c < 40; c++) out[idx * 40 + c] = acc[c] - lse;
}

// ---------------- launch ---------------------------------------------------
extern "C" void kernel_launch(void* const* d_in, const int* in_sizes, int n_in,
                              void* d_out, int out_size) {
    const float* x  = (const float*)d_in[0];
    const int*   ei = (const int*)d_in[1];     // int32! (JAX x64 disabled)
    const float* ew = (const float*)d_in[2];
    const float* Wf = (const float*)d_in[3];
    const float* bf = (const float*)d_in[4];
    const float* W1 = (const float*)d_in[5];
    const float* b1 = (const float*)d_in[6];
    const float* W2 = (const float*)d_in[7];
    const float* b2 = (const float*)d_in[8];
    const float* Wo = (const float*)d_in[9];
    const float* bo = (const float*)d_in[10];
    float* out = (float*)d_out;

    float* bufA; float* bufB;
    cudaGetSymbolAddress((void**)&bufA, g_bufA);
    cudaGetSymbolAddress((void**)&bufB, g_bufB);

    k_init   <<<(NN + 255) / 256, 256>>>();
    k_scatter<<<EE / 512, 256>>>(ei, ew);
    k_deg    <<<NN / 16, 256>>>();

    k_gemm1  <<<RB * KCH, 256>>>(x, Wf);
    k_gfin   <<<(NN * 4 + 255) / 256, 256>>>(bf);

    k_agg    <<<NN * 16 / 256, 256>>>(bufA, bufB, W1, b1, 1);
    k_agg    <<<NN * 16 / 256, 256>>>(bufB, bufA, W2, b2, 0);

    k_out    <<<(NN + 255) / 256, 256>>>(Wo, bo, out);
}

// round 13
// speedup vs baseline: 1.3495x; 1.1421x over previous
#include <cuda_runtime.h>

#define NN 100000
#define EE 3200000
#define FIN 512
#define HH 16
#define CC 40
#define CAP 128            // bucket capacity per node (deg~Poisson(32), 17-sigma safe)
#define KCH 4              // gemm1 K-split chunks
#define RB  391            // row-blocks in gemm1 = ceil(NN/256)

typedef unsigned long long u64;

// ---------------- scratch (device globals; no allocation allowed) ----------
__device__ int   g_cnt[NN];
__device__ float g_dinv[NN];
__device__ __align__(16) int2  g_csr[NN * CAP];     // {row, ew_bits}, bucketed
__device__ __align__(16) float g_part[KCH * NN * HH];
__device__ __align__(16) float g_bufA[NN * HH];
__device__ __align__(16) float g_bufB[NN * HH];

// ---------------- packed f32x2 helpers -------------------------------------
__device__ __forceinline__ void ffma2(u64& d, u64 a, u64 b) {
    asm("fma.rn.f32x2 %0, %1, %2, %0;" : "+l"(d) : "l"(a), "l"(b));
}
__device__ __forceinline__ u64 pack2(float a, float b) {
    u64 r; asm("mov.b64 %0, {%1, %2};" : "=l"(r) : "f"(a), "f"(b)); return r;
}
__device__ __forceinline__ float2 unpack2(u64 v) {
    float2 r; asm("mov.b64 {%0, %1}, %2;" : "=f"(r.x), "=f"(r.y) : "l"(v)); return r;
}

// ---------------- init: zero counts ----------------------------------------
__global__ void k_init() {
    int i = blockIdx.x * blockDim.x + threadIdx.x;
    if (i < NN) g_cnt[i] = 0;
}

// ---------------- scatter: bucketed CSR, raw ew, ONE atomic per edge -------
// edge_index is int32 (JAX x64 disabled). 2 edges per thread, vectorized.
__global__ void k_scatter(const int* __restrict__ ei,
                          const float* __restrict__ ew) {
    int e2 = (blockIdx.x * blockDim.x + threadIdx.x) * 2;
    int2   r = *(const int2*)(ei + e2);
    int2   c = *(const int2*)(ei + EE + e2);
    float2 w = *(const float2*)(ew + e2);
    int s0 = atomicAdd(&g_cnt[c.x], 1);
    g_csr[(c.x << 7) + s0] = make_int2(r.x, __float_as_int(w.x));
    int s1 = atomicAdd(&g_cnt[c.y], 1);
    g_csr[(c.y << 7) + s1] = make_int2(r.y, __float_as_int(w.y));
}

// ---------------- weighted degree -> dinv (sequential sweep, no atomics) ---
__global__ __launch_bounds__(256) void k_deg() {
    int tid  = blockIdx.x * 256 + threadIdx.x;
    int node = tid >> 4;
    int l    = tid & 15;
    int cnt  = g_cnt[node];
    int base = node << 7;
    float s = 0.f;
    for (int i = l; i < cnt; i += 16)
        s += __int_as_float(g_csr[base + i].y);
#pragma unroll
    for (int d = 8; d; d >>= 1) s += __shfl_xor_sync(0xFFFFFFFFu, s, d, 16);
    if (l == 0) g_dinv[node] = rsqrtf(1.0f + s);   // +1 = self loop
}

// ---------------- gemm1 split-K, W in smem, float2 x reads -----------------
// 256 threads = 8 warps; warp w: khalf = w&1 (uniform!), rowgroup = w>>1.
// Thread: 2 rows x 8 outputs (khalf) = 8 u64 acc. Block covers 256 rows.
__global__ __launch_bounds__(256) void k_gemm1(const float* __restrict__ x,
                                               const float* __restrict__ W) {
    __shared__ float Ws[128 * 16];        // chunk's W slice, 8 KB
    __shared__ float xs[256 * 18];        // 256 rows x 16 feats, pitch 18
    int t = threadIdx.x;
    int lane = t & 31;
    int w = t >> 5;
    int khalf = w & 1;                    // warp-uniform -> broadcast W LDS
    int rg = w >> 1;                      // row group 0..3 (64 rows each)
    int r0l = rg * 64 + lane;             // local rows
    int r1l = r0l + 32;
    int rowblk = blockIdx.x % RB;
    int chunk  = blockIdx.x / RB;         // K-chunk of 128 feats
    int rowbase = rowblk * 256;

    // stage W chunk slice once: rows chunk*128..+127, 16 cols = 2048 floats
    {
        const float4* W4 = (const float4*)(W + chunk * 128 * 16);
        float4* Ws4 = (float4*)Ws;
        Ws4[t]       = W4[t];
        Ws4[t + 256] = W4[t + 256];
    }

    u64 acc0[4], acc1[4];
#pragma unroll
    for (int q = 0; q < 4; q++) { acc0[q] = 0ull; acc1[q] = 0ull; }

    const float4* x4 = (const float4*)x;

    for (int tile = 0; tile < 8; tile++) {         // 8 x 16 = 128 feats
        int fbase4 = chunk * 32 + tile * 4;        // in float4 units
        __syncthreads();
        // stage 256 rows x 16 feats: 4 coalesced float4 loads per thread
#pragma unroll
        for (int i = 0; i < 4; i++) {
            int idx = i * 256 + t;                 // 0..1023 float4s
            int r = idx >> 2, f4 = idx & 3;
            int grow = rowbase + r;
            float4 v = make_float4(0.f, 0.f, 0.f, 0.f);
            if (grow < NN) v = x4[grow * (FIN / 4) + fbase4 + f4];
            float* dst = &xs[r * 18 + f4 * 4];
            *(float2*)(dst)     = make_float2(v.x, v.y);
            *(float2*)(dst + 2) = make_float2(v.z, v.w);
        }
        __syncthreads();
#pragma unroll
        for (int f2 = 0; f2 < 8; f2++) {
            int fo = (tile * 16 + f2 * 2) * 16 + khalf * 8;
            ulonglong2 w00 = *(const ulonglong2*)(Ws + fo);       // f even
            ulonglong2 w01 = *(const ulonglong2*)(Ws + fo + 4);
            ulonglong2 w10 = *(const ulonglong2*)(Ws + fo + 16);  // f odd
            ulonglong2 w11 = *(const ulonglong2*)(Ws + fo + 20);
            float2 xa = *(const float2*)(xs + r0l * 18 + f2 * 2);
            float2 xb = *(const float2*)(xs + r1l * 18 + f2 * 2);
            u64 xa0 = pack2(xa.x, xa.x), xa1 = pack2(xa.y, xa.y);
            u64 xb0 = pack2(xb.x, xb.x), xb1 = pack2(xb.y, xb.y);
            ffma2(acc0[0], xa0, w00.x); ffma2(acc0[1], xa0, w00.y);
            ffma2(acc0[2], xa0, w01.x); ffma2(acc0[3], xa0, w01.y);
            ffma2(acc0[0], xa1, w10.x); ffma2(acc0[1], xa1, w10.y);
            ffma2(acc0[2], xa1, w11.x); ffma2(acc0[3], xa1, w11.y);
            ffma2(acc1[0], xb0, w00.x); ffma2(acc1[1], xb0, w00.y);
            ffma2(acc1[2], xb0, w01.x); ffma2(acc1[3], xb0, w01.y);
            ffma2(acc1[0], xb1, w10.x); ffma2(acc1[1], xb1, w10.y);
            ffma2(acc1[2], xb1, w11.x); ffma2(acc1[3], xb1, w11.y);
        }
    }
    float4* out4 = (float4*)(g_part + chunk * NN * HH);
    int row0 = rowbase + r0l;
    int row1 = rowbase + r1l;
    if (row0 < NN) {
        float2 a = unpack2(acc0[0]); float2 b = unpack2(acc0[1]);
        float2 c = unpack2(acc0[2]); float2 d = unpack2(acc0[3]);
        out4[row0 * 4 + khalf * 2 + 0] = make_float4(a.x, a.y, b.x, b.y);
        out4[row0 * 4 + khalf * 2 + 1] = make_float4(c.x, c.y, d.x, d.y);
    }
    if (row1 < NN) {
        float2 a = unpack2(acc1[0]); float2 b = unpack2(acc1[1]);
        float2 c = unpack2(acc1[2]); float2 d = unpack2(acc1[3]);
        out4[row1 * 4 + khalf * 2 + 0] = make_float4(a.x, a.y, b.x, b.y);
        out4[row1 * 4 + khalf * 2 + 1] = make_float4(c.x, c.y, d.x, d.y);
    }
}

// ---------------- gemm1 reduce: bufA = dinv * relu(sum parts + b) ----------
__global__ __launch_bounds__(256) void k_gfin(const float* __restrict__ b) {
    int idx = blockIdx.x * 256 + threadIdx.x;      // float4 index
    if (idx >= NN * 4) return;
    const float4* p = (const float4*)g_part;
    float4 p0 = p[idx];
    float4 p1 = p[idx + NN * 4];
    float4 p2 = p[idx + NN * 8];
    float4 p3 = p[idx + NN * 12];
    int row = idx >> 2, k4 = idx & 3;
    float4 bb = __ldg(&((const float4*)b)[k4]);
    float dv = g_dinv[row];
    float4 o;
    o.x = fmaxf(p0.x + p1.x + p2.x + p3.x + bb.x, 0.f) * dv;
    o.y = fmaxf(p0.y + p1.y + p2.y + p3.y + bb.y, 0.f) * dv;
    o.z = fmaxf(p0.z + p1.z + p2.z + p3.z + bb.z, 0.f) * dv;
    o.w = fmaxf(p0.w + p1.w + p2.w + p3.w + bb.w, 0.f) * dv;
    ((float4*)g_bufA)[idx] = o;
}

// ---------------- fused conv: hout = [dinv*] relu((A @ hin) @ W + b) -------
// hin is pre-scaled by dinv (h' = dinv*h):
//   agg_c = dinv_c * ( sum_e ew_e * h'_r  +  h'_c )
// half-warp per node; 16-edge chunks read as 8x int4 (2 edges per LDG.128).
__global__ __launch_bounds__(256) void k_agg(const float* __restrict__ hin,
                                             float* __restrict__ hout,
                                             const float* __restrict__ W,
                                             const float* __restrict__ bias,
                                             int premul) {
    __shared__ float Ws[256];
    __shared__ float bs[16];
    __shared__ float hb[256];
    Ws[threadIdx.x] = W[threadIdx.x];
    if (threadIdx.x < 16) bs[threadIdx.x] = bias[threadIdx.x];
    __syncthreads();

    int tid = blockIdx.x * 256 + threadIdx.x;     // grid = NN*16/256 exactly
    int node = tid >> 4;
    int k = tid & 15;

    int cnt  = g_cnt[node];
    int base = node << 7;
    float acc = hin[node * 16 + k];               // self loop (already scaled)

    const int4* csr4 = (const int4*)g_csr;        // 2 edges per int4
    for (int e = 0; e < cnt; e += 16) {
#pragma unroll
        for (int j = 0; j < 8; j++) {
            int idx = e + j * 2;
            if (idx < cnt) {
                int4 pq = __ldg(&csr4[(base + idx) >> 1]);
                acc += __int_as_float(pq.y) * __ldg(&hin[pq.x * 16 + k]);
                if (idx + 1 < cnt)
                    acc += __int_as_float(pq.w) * __ldg(&hin[pq.z * 16 + k]);
            }
        }
    }
    float dv = g_dinv[node];
    acc *= dv;

    // 16x16 transform: exchange aggregated feats within the half-warp
    hb[threadIdx.x] = acc;
    __syncwarp();
    int hbase = threadIdx.x & ~15;
    float o = bs[k];
#pragma unroll
    for (int f = 0; f < 16; f++) o += hb[hbase + f] * Ws[f * 16 + k];
    float res = fmaxf(o, 0.0f);
    if (premul) res *= dv;                        // pre-scale for next layer
    hout[node * 16 + k] = res;
}

// ---------------- output: logits (16x40) + log_softmax --------------------
__global__ __launch_bounds__(256) void k_out(const float* __restrict__ Wo,
                                             const float* __restrict__ bo,
                                             float* __restrict__ out) {
    __shared__ float Ws[16 * 40];
    __shared__ float bs[40];
    for (int i = threadIdx.x; i < 640; i += 256) Ws[i] = Wo[i];
    if (threadIdx.x < 40) bs[threadIdx.x] = bo[threadIdx.x];
    __syncthreads();
    int idx = blockIdx.x * blockDim.x + threadIdx.x;
    if (idx >= NN) return;

    const float4* in4 = (const float4*)g_bufA;
    float hx[16];
#pragma unroll
    for (int q = 0; q < 4; q++) {
        float4 v = in4[idx * 4 + q];
        hx[q * 4 + 0] = v.x; hx[q * 4 + 1] = v.y;
        hx[q * 4 + 2] = v.z; hx[q * 4 + 3] = v.w;
    }
    float acc[40];
#pragma unroll
    for (int c = 0; c < 40; c++) acc[c] = bs[c];
#pragma unroll
    for (int f = 0; f < 16; f++) {
        float xv = hx[f];
#pragma unroll
        for (int c = 0; c < 40; c++) acc[c] += xv * Ws[f * 40 + c];
    }
    float m = acc[0];
#pragma unroll
    for (int c = 1; c < 40; c++) m = fmaxf(m, acc[c]);
    float s = 0.f;
#pragma unroll
    for (int c = 0; c < 40; c++) s += __expf(acc[c] - m);
    float lse = m + __logf(s);
#pragma unroll
    for (int c = 0; c < 40; c++) out[idx * 40 + c] = acc[c] - lse;
}

// ---------------- launch ---------------------------------------------------
extern "C" void kernel_launch(void* const* d_in, const int* in_sizes, int n_in,
                              void* d_out, int out_size) {
    const float* x  = (const float*)d_in[0];
    const int*   ei = (const int*)d_in[1];     // int32! (JAX x64 disabled)
    const float* ew = (const float*)d_in[2];
    const float* Wf = (const float*)d_in[3];
    const float* bf = (const float*)d_in[4];
    const float* W1 = (const float*)d_in[5];
    const float* b1 = (const float*)d_in[6];
    const float* W2 = (const float*)d_in[7];
    const float* b2 = (const float*)d_in[8];
    const float* Wo = (const float*)d_in[9];
    const float* bo = (const float*)d_in[10];
    float* out = (float*)d_out;

    float* bufA; float* bufB;
    cudaGetSymbolAddress((void**)&bufA, g_bufA);
    cudaGetSymbolAddress((void**)&bufB, g_bufB);

    k_init   <<<(NN + 255) / 256, 256>>>();
    k_scatter<<<EE / 512, 256>>>(ei, ew);
    k_deg    <<<NN / 16, 256>>>();

    k_gemm1  <<<RB * KCH, 256>>>(x, Wf);
    k_gfin   <<<(NN * 4 + 255) / 256, 256>>>(bf);

    k_agg    <<<NN * 16 / 256, 256>>>(bufA, bufB, W1, b1, 1);
    k_agg    <<<NN * 16 / 256, 256>>>(bufB, bufA, W2, b2, 0);

    k_out    <<<(NN + 255) / 256, 256>>>(Wo, bo, out);
}

// round 14
// speedup vs baseline: 1.4058x; 1.0418x over previous
#include <cuda_runtime.h>

#define NN 100000
#define EE 3200000
#define FIN 512
#define HH 16
#define CC 40
#define CAP 128            // bucket capacity per node (deg~Poisson(32), 17-sigma safe)
#define KCH 4              // gemm1 K-split chunks
#define RB  391            // row-blocks in gemm1 = ceil(NN/256)

typedef unsigned long long u64;

// ---------------- scratch (device globals; no allocation allowed) ----------
__device__ u64   g_pack[NN];         // (slots<<40) | fixed24(sum ew)
__device__ float g_dinv[NN];
__device__ __align__(16) int2  g_csr[NN * CAP];     // {row, ew_bits}, bucketed
__device__ __align__(16) float g_part[KCH * NN * HH];
__device__ __align__(16) float g_bufA[NN * HH];
__device__ __align__(16) float g_bufB[NN * HH];

// ---------------- packed f32x2 helpers -------------------------------------
__device__ __forceinline__ void ffma2(u64& d, u64 a, u64 b) {
    asm("fma.rn.f32x2 %0, %1, %2, %0;" : "+l"(d) : "l"(a), "l"(b));
}
__device__ __forceinline__ u64 add2(u64 a, u64 b) {
    u64 r; asm("add.rn.f32x2 %0, %1, %2;" : "=l"(r) : "l"(a), "l"(b)); return r;
}
__device__ __forceinline__ u64 pack2(float a, float b) {
    u64 r; asm("mov.b64 %0, {%1, %2};" : "=l"(r) : "f"(a), "f"(b)); return r;
}
__device__ __forceinline__ float2 unpack2(u64 v) {
    float2 r; asm("mov.b64 {%0, %1}, %2;" : "=f"(r.x), "=f"(r.y) : "l"(v)); return r;
}

// ---------------- init: zero pack -------------------------------------------
__global__ void k_init() {
    int i = blockIdx.x * blockDim.x + threadIdx.x;
    if (i < NN) g_pack[i] = 0ull;
}

// ---------------- scatter: ONE u64 atomic per edge gives slot + sums ew ----
// edge_index is int32 (JAX x64 disabled). 4 edges per thread, vectorized.
__global__ void k_scatter(const int* __restrict__ ei,
                          const float* __restrict__ ew) {
    int e4 = (blockIdx.x * blockDim.x + threadIdx.x) * 4;
    int4   r = *(const int4*)(ei + e4);
    int4   c = *(const int4*)(ei + EE + e4);
    float4 w = *(const float4*)(ew + e4);
    u64 p, old;
    p = (1ull << 40) | (u64)__float2uint_rn(w.x * 16777216.0f);
    old = atomicAdd(&g_pack[c.x], p);
    g_csr[(c.x << 7) + (int)(old >> 40)] = make_int2(r.x, __float_as_int(w.x));
    p = (1ull << 40) | (u64)__float2uint_rn(w.y * 16777216.0f);
    old = atomicAdd(&g_pack[c.y], p);
    g_csr[(c.y << 7) + (int)(old >> 40)] = make_int2(r.y, __float_as_int(w.y));
    p = (1ull << 40) | (u64)__float2uint_rn(w.z * 16777216.0f);
    old = atomicAdd(&g_pack[c.z], p);
    g_csr[(c.z << 7) + (int)(old >> 40)] = make_int2(r.z, __float_as_int(w.z));
    p = (1ull << 40) | (u64)__float2uint_rn(w.w * 16777216.0f);
    old = atomicAdd(&g_pack[c.w], p);
    g_csr[(c.w << 7) + (int)(old >> 40)] = make_int2(r.w, __float_as_int(w.w));
}

// ---------------- gemm1 split-K, W in smem, f-split warps ------------------
// 8 warps: khalf=w&1 (out half, warp-uniform), rg=(w>>1)&1 (128-row half),
// fh=w>>2 (f half of each tile). Thread: 4 rows x 8 outputs, half the f.
// fh pairs reduce via smem at the end.
__global__ __launch_bounds__(256) void k_gemm1(const float* __restrict__ x,
                                               const float* __restrict__ W) {
    __shared__ float Ws[128 * 16];               // chunk's W slice, 8 KB
    __shared__ __align__(16) float xs[256 * 18]; // staging; reused for reduce
    int t = threadIdx.x;
    int lane = t & 31;
    int w = t >> 5;
    int khalf = w & 1;
    int rg = (w >> 1) & 1;                       // row half (128 rows)
    int fh = w >> 2;                             // f half of tile
    int rbase = rg * 128 + lane;                 // local row of rr=0
    int rowblk = blockIdx.x % RB;
    int chunk  = blockIdx.x / RB;                // K-chunk of 128 feats
    int rowbase = rowblk * 256;

    // stage W chunk slice once: 128 rows x 16 cols = 2048 floats
    {
        const float4* W4 = (const float4*)(W + chunk * 128 * 16);
        float4* Ws4 = (float4*)Ws;
        Ws4[t]       = W4[t];
        Ws4[t + 256] = W4[t + 256];
    }

    u64 acc[4][4];
#pragma unroll
    for (int rr = 0; rr < 4; rr++)
#pragma unroll
        for (int q = 0; q < 4; q++) acc[rr][q] = 0ull;

    const float4* x4 = (const float4*)x;

    for (int tile = 0; tile < 8; tile++) {       // 8 x 16 = 128 feats
        int fbase4 = chunk * 32 + tile * 4;      // in float4 units
        __syncthreads();
        // stage 256 rows x 16 feats: 4 coalesced float4 loads per thread
#pragma unroll
        for (int i = 0; i < 4; i++) {
            int idx = i * 256 + t;               // 0..1023 float4s
            int r = idx >> 2, f4 = idx & 3;
            int grow = rowbase + r;
            float4 v = make_float4(0.f, 0.f, 0.f, 0.f);
            if (grow < NN) v = x4[grow * (FIN / 4) + fbase4 + f4];
            float* dst = &xs[r * 18 + f4 * 4];
            *(float2*)(dst)     = make_float2(v.x, v.y);
            *(float2*)(dst + 2) = make_float2(v.z, v.w);
        }
        __syncthreads();
#pragma unroll
        for (int f2i = 0; f2i < 4; f2i++) {
            int f2 = fh * 4 + f2i;               // f-pair 0..7
            int fo = (tile * 16 + f2 * 2) * 16 + khalf * 8;
            ulonglong2 w00 = *(const ulonglong2*)(Ws + fo);       // f even
            ulonglong2 w01 = *(const ulonglong2*)(Ws + fo + 4);
            ulonglong2 w10 = *(const ulonglong2*)(Ws + fo + 16);  // f odd
            ulonglong2 w11 = *(const ulonglong2*)(Ws + fo + 20);
#pragma unroll
            for (int rr = 0; rr < 4; rr++) {
                float2 xv = *(const float2*)(xs + (rbase + rr * 32) * 18 + f2 * 2);
                u64 x0 = pack2(xv.x, xv.x);
                u64 x1 = pack2(xv.y, xv.y);
                ffma2(acc[rr][0], x0, w00.x); ffma2(acc[rr][1], x0, w00.y);
                ffma2(acc[rr][2], x0, w01.x); ffma2(acc[rr][3], x0, w01.y);
                ffma2(acc[rr][0], x1, w10.x); ffma2(acc[rr][1], x1, w10.y);
                ffma2(acc[rr][2], x1, w11.x); ffma2(acc[rr][3], x1, w11.y);
            }
        }
    }

    // reduce fh pairs: fh1 stores partials, fh0 adds
    __syncthreads();
    u64* red = (u64*)xs;                         // 128 threads x 16 u64 = 16KB
    int t128 = t & 127;
    if (fh == 1) {
#pragma unroll
        for (int rr = 0; rr < 4; rr++)
#pragma unroll
            for (int q = 0; q < 4; q++) red[t128 * 16 + rr * 4 + q] = acc[rr][q];
    }
    __syncthreads();
    if (fh == 0) {
        float4* out4 = (float4*)(g_part + chunk * NN * HH);
#pragma unroll
        for (int rr = 0; rr < 4; rr++) {
            int row = rowbase + rbase + rr * 32;
            if (row < NN) {
                u64 s0 = add2(acc[rr][0], red[t128 * 16 + rr * 4 + 0]);
                u64 s1 = add2(acc[rr][1], red[t128 * 16 + rr * 4 + 1]);
                u64 s2 = add2(acc[rr][2], red[t128 * 16 + rr * 4 + 2]);
                u64 s3 = add2(acc[rr][3], red[t128 * 16 + rr * 4 + 3]);
                float2 a = unpack2(s0); float2 b = unpack2(s1);
                float2 c = unpack2(s2); float2 d = unpack2(s3);
                out4[row * 4 + khalf * 2 + 0] = make_float4(a.x, a.y, b.x, b.y);
                out4[row * 4 + khalf * 2 + 1] = make_float4(c.x, c.y, d.x, d.y);
            }
        }
    }
}

// ---------------- gemm1 reduce: bufA = dinv * relu(sum parts + b) ----------
// also materializes g_dinv (from packed fixed-point degree) for k_agg.
__global__ __launch_bounds__(256) void k_gfin(const float* __restrict__ b) {
    int idx = blockIdx.x * 256 + threadIdx.x;      // float4 index
    if (idx >= NN * 4) return;
    const float4* p = (const float4*)g_part;
    float4 p0 = p[idx];
    float4 p1 = p[idx + NN * 4];
    float4 p2 = p[idx + NN * 8];
    float4 p3 = p[idx + NN * 12];
    int row = idx >> 2, k4 = idx & 3;
    float4 bb = __ldg(&((const float4*)b)[k4]);
    u64 pk = g_pack[row];
    float deg = 1.0f + (float)(pk & 0xFFFFFFFFFFull) * 5.9604645e-8f;
    float dv = rsqrtf(deg);
    if (k4 == 0) g_dinv[row] = dv;
    float4 o;
    o.x = fmaxf(p0.x + p1.x + p2.x + p3.x + bb.x, 0.f) * dv;
    o.y = fmaxf(p0.y + p1.y + p2.y + p3.y + bb.y, 0.f) * dv;
    o.z = fmaxf(p0.z + p1.z + p2.z + p3.z + bb.z, 0.f) * dv;
    o.w = fmaxf(p0.w + p1.w + p2.w + p3.w + bb.w, 0.f) * dv;
    ((float4*)g_bufA)[idx] = o;
}

// ---------------- fused conv: hout = [dinv*] relu((A @ hin) @ W + b) -------
// hin is pre-scaled by dinv (h' = dinv*h):
//   agg_c = dinv_c * ( sum_e ew_e * h'_r  +  h'_c )
// half-warp per node; 16-edge chunks read as 8x int4 (2 edges per LDG.128).
__global__ __launch_bounds__(256) void k_agg(const float* __restrict__ hin,
                                             float* __restrict__ hout,
                                             const float* __restrict__ W,
                                             const float* __restrict__ bias,
                                             int premul) {
    __shared__ float Ws[256];
    __shared__ float bs[16];
    __shared__ float hb[256];
    Ws[threadIdx.x] = W[threadIdx.x];
    if (threadIdx.x < 16) bs[threadIdx.x] = bias[threadIdx.x];
    __syncthreads();

    int tid = blockIdx.x * 256 + threadIdx.x;     // grid = NN*16/256 exactly
    int node = tid >> 4;
    int k = tid & 15;

    int cnt  = (int)(g_pack[node] >> 40);
    int base = node << 7;
    float acc = hin[node * 16 + k];               // self loop (already scaled)

    const int4* csr4 = (const int4*)g_csr;        // 2 edges per int4
    for (int e = 0; e < cnt; e += 16) {
#pragma unroll
        for (int j = 0; j < 8; j++) {
            int idx = e + j * 2;
            if (idx < cnt) {
                int4 pq = __ldg(&csr4[(base + idx) >> 1]);
                acc += __int_as_float(pq.y) * __ldg(&hin[pq.x * 16 + k]);
                if (idx + 1 < cnt)
                    acc += __int_as_float(pq.w) * __ldg(&hin[pq.z * 16 + k]);
            }
        }
    }
    float dv = g_dinv[node];
    acc *= dv;

    // 16x16 transform: exchange aggregated feats within the half-warp
    hb[threadIdx.x] = acc;
    __syncwarp();
    int hbase = threadIdx.x & ~15;
    float o = bs[k];
#pragma unroll
    for (int f = 0; f < 16; f++) o += hb[hbase + f] * Ws[f * 16 + k];
    float res = fmaxf(o, 0.0f);
    if (premul) res *= dv;                        // pre-scale for next layer
    hout[node * 16 + k] = res;
}

// ---------------- output: logits (16x40) + log_softmax --------------------
__global__ __launch_bounds__(256) void k_out(const float* __restrict__ Wo,
                                             const float* __restrict__ bo,
                                             float* __restrict__ out) {
    __shared__ float Ws[16 * 40];
    __shared__ float bs[40];
    for (int i = threadIdx.x; i < 640; i += 256) Ws[i] = Wo[i];
    if (threadIdx.x < 40) bs[threadIdx.x] = bo[threadIdx.x];
    __syncthreads();
    int idx = blockIdx.x * blockDim.x + threadIdx.x;
    if (idx >= NN) return;

    const float4* in4 = (const float4*)g_bufA;
    float hx[16];
#pragma unroll
    for (int q = 0; q < 4; q++) {
        float4 v = in4[idx * 4 + q];
        hx[q * 4 + 0] = v.x; hx[q * 4 + 1] = v.y;
        hx[q * 4 + 2] = v.z; hx[q * 4 + 3] = v.w;
    }
    float acc[40];
#pragma unroll
    for (int c = 0; c < 40; c++) acc[c] = bs[c];
#pragma unroll
    for (int f = 0; f < 16; f++) {
        float xv = hx[f];
#pragma unroll
        for (int c = 0; c < 40; c++) acc[c] += xv * Ws[f * 40 + c];
    }
    float m = acc[0];
#pragma unroll
    for (int c = 1; c < 40; c++) m = fmaxf(m, acc[c]);
    float s = 0.f;
#pragma unroll
    for (int c = 0; c < 40; c++) s += __expf(acc[c] - m);
    float lse = m + __logf(s);
#pragma unroll
    for (int c = 0; c < 40; c++) out[idx * 40 + c] = acc[c] - lse;
}

// ---------------- launch ---------------------------------------------------
extern "C" void kernel_launch(void* const* d_in, const int* in_sizes, int n_in,
                              void* d_out, int out_size) {
    const float* x  = (const float*)d_in[0];
    const int*   ei = (const int*)d_in[1];     // int32! (JAX x64 disabled)
    const float* ew = (const float*)d_in[2];
    const float* Wf = (const float*)d_in[3];
    const float* bf = (const float*)d_in[4];
    const float* W1 = (const float*)d_in[5];
    const float* b1 = (const float*)d_in[6];
    const float* W2 = (const float*)d_in[7];
    const float* b2 = (const float*)d_in[8];
    const float* Wo = (const float*)d_in[9];
    const float* bo = (const float*)d_in[10];
    float* out = (float*)d_out;

    float* bufA; float* bufB;
    cudaGetSymbolAddress((void**)&bufA, g_bufA);
    cudaGetSymbolAddress((void**)&bufB, g_bufB);

    k_init   <<<(NN + 255) / 256, 256>>>();
    k_scatter<<<EE / 1024, 256>>>(ei, ew);

    k_gemm1  <<<RB * KCH, 256>>>(x, Wf);
    k_gfin   <<<(NN * 4 + 255) / 256, 256>>>(bf);

    k_agg    <<<NN * 16 / 256, 256>>>(bufA, bufB, W1, b1, 1);
    k_agg    <<<NN * 16 / 256, 256>>>(bufB, bufA, W2, b2, 0);

    k_out    <<<(NN + 255) / 256, 256>>>(Wo, bo, out);
}

// round 15
// speedup vs baseline: 1.4661x; 1.0429x over previous
#include <cuda_runtime.h>

#define NN 100000
#define EE 3200000
#define FIN 512
#define HH 16
#define CC 40
#define CAP 128            // bucket capacity per node (deg~Poisson(32), 17-sigma safe)
#define KCH 4              // gemm1 K-split chunks
#define RB  391            // row-blocks in gemm1 = ceil(NN/256)
#define SB  3125           // scatter blocks (EE / 1024)
#define FUSED_GRID 4692    // 1564 gemm (bi%3==0) + 3128 scatter slots

typedef unsigned long long u64;

// ---------------- scratch (device globals; no allocation allowed) ----------
__device__ u64   g_pack[NN];         // (slots<<40) | fixed24(sum ew)
__device__ float g_dinv[NN];
__device__ __align__(16) int2  g_csr[NN * CAP];     // {row, ew_bits}, bucketed
__device__ __align__(16) float g_part[KCH * NN * HH];
__device__ __align__(16) float g_bufA[NN * HH];
__device__ __align__(16) float g_bufB[NN * HH];

// ---------------- packed f32x2 helpers -------------------------------------
__device__ __forceinline__ void ffma2(u64& d, u64 a, u64 b) {
    asm("fma.rn.f32x2 %0, %1, %2, %0;" : "+l"(d) : "l"(a), "l"(b));
}
__device__ __forceinline__ u64 add2(u64 a, u64 b) {
    u64 r; asm("add.rn.f32x2 %0, %1, %2;" : "=l"(r) : "l"(a), "l"(b)); return r;
}
__device__ __forceinline__ u64 pack2(float a, float b) {
    u64 r; asm("mov.b64 %0, {%1, %2};" : "=l"(r) : "f"(a), "f"(b)); return r;
}
__device__ __forceinline__ float2 unpack2(u64 v) {
    float2 r; asm("mov.b64 {%0, %1}, %2;" : "=f"(r.x), "=f"(r.y) : "l"(v)); return r;
}

// ---------------- init: zero pack -------------------------------------------
__global__ void k_init() {
    int i = blockIdx.x * blockDim.x + threadIdx.x;
    if (i < NN) g_pack[i] = 0ull;
}

// ---------------- FUSED: scatter + gemm1 (independent work, one launch) ----
// bi%3==0  -> gemm1 block   (bid = bi/3, 0..1563)
// bi%3!=0  -> scatter block (sid = 2*(bi/3)+(bi%3)-1, 0..3127; >=SB idle)
__global__ __launch_bounds__(256) void k_fused(const float* __restrict__ x,
                                               const float* __restrict__ W,
                                               const int*   __restrict__ ei,
                                               const float* __restrict__ ew) {
    __shared__ float Ws[128 * 16];               // gemm W slice, 8 KB
    __shared__ __align__(16) float xs[256 * 18]; // gemm staging / reduce
    int bi = blockIdx.x;
    int t = threadIdx.x;

    if (bi % 3 != 0) {
        // ---------------- scatter body ----------------
        int sid = (bi / 3) * 2 + (bi % 3) - 1;
        if (sid >= SB) return;
        int e4 = (sid * 256 + t) * 4;
        int4   r = *(const int4*)(ei + e4);
        int4   c = *(const int4*)(ei + EE + e4);
        float4 w = *(const float4*)(ew + e4);
        u64 p, old;
        p = (1ull << 40) | (u64)__float2uint_rn(w.x * 16777216.0f);
        old = atomicAdd(&g_pack[c.x], p);
        g_csr[(c.x << 7) + (int)(old >> 40)] = make_int2(r.x, __float_as_int(w.x));
        p = (1ull << 40) | (u64)__float2uint_rn(w.y * 16777216.0f);
        old = atomicAdd(&g_pack[c.y], p);
        g_csr[(c.y << 7) + (int)(old >> 40)] = make_int2(r.y, __float_as_int(w.y));
        p = (1ull << 40) | (u64)__float2uint_rn(w.z * 16777216.0f);
        old = atomicAdd(&g_pack[c.z], p);
        g_csr[(c.z << 7) + (int)(old >> 40)] = make_int2(r.z, __float_as_int(w.z));
        p = (1ull << 40) | (u64)__float2uint_rn(w.w * 16777216.0f);
        old = atomicAdd(&g_pack[c.w], p);
        g_csr[(c.w << 7) + (int)(old >> 40)] = make_int2(r.w, __float_as_int(w.w));
        return;
    }

    // ---------------- gemm1 body (f-split warps, W in smem) ----------------
    int bid = bi / 3;
    int lane = t & 31;
    int w = t >> 5;
    int khalf = w & 1;
    int rg = (w >> 1) & 1;                       // row half (128 rows)
    int fh = w >> 2;                             // f half of tile
    int rbase = rg * 128 + lane;                 // local row of rr=0
    int rowblk = bid % RB;
    int chunk  = bid / RB;                       // K-chunk of 128 feats
    int rowbase = rowblk * 256;

    // stage W chunk slice once: 128 rows x 16 cols = 2048 floats
    {
        const float4* W4 = (const float4*)(W + chunk * 128 * 16);
        float4* Ws4 = (float4*)Ws;
        Ws4[t]       = W4[t];
        Ws4[t + 256] = W4[t + 256];
    }

    u64 acc[4][4];
#pragma unroll
    for (int rr = 0; rr < 4; rr++)
#pragma unroll
        for (int q = 0; q < 4; q++) acc[rr][q] = 0ull;

    const float4* x4 = (const float4*)x;

    for (int tile = 0; tile < 8; tile++) {       // 8 x 16 = 128 feats
        int fbase4 = chunk * 32 + tile * 4;      // in float4 units
        __syncthreads();
#pragma unroll
        for (int i = 0; i < 4; i++) {
            int idx = i * 256 + t;               // 0..1023 float4s
            int r = idx >> 2, f4 = idx & 3;
            int grow = rowbase + r;
            float4 v = make_float4(0.f, 0.f, 0.f, 0.f);
            if (grow < NN) v = x4[grow * (FIN / 4) + fbase4 + f4];
            float* dst = &xs[r * 18 + f4 * 4];
            *(float2*)(dst)     = make_float2(v.x, v.y);
            *(float2*)(dst + 2) = make_float2(v.z, v.w);
        }
        __syncthreads();
#pragma unroll
        for (int f2i = 0; f2i < 4; f2i++) {
            int f2 = fh * 4 + f2i;               // f-pair 0..7
            int fo = (tile * 16 + f2 * 2) * 16 + khalf * 8;
            ulonglong2 w00 = *(const ulonglong2*)(Ws + fo);       // f even
            ulonglong2 w01 = *(const ulonglong2*)(Ws + fo + 4);
            ulonglong2 w10 = *(const ulonglong2*)(Ws + fo + 16);  // f odd
            ulonglong2 w11 = *(const ulonglong2*)(Ws + fo + 20);
#pragma unroll
            for (int rr = 0; rr < 4; rr++) {
                float2 xv = *(const float2*)(xs + (rbase + rr * 32) * 18 + f2 * 2);
                u64 x0 = pack2(xv.x, xv.x);
                u64 x1 = pack2(xv.y, xv.y);
                ffma2(acc[rr][0], x0, w00.x); ffma2(acc[rr][1], x0, w00.y);
                ffma2(acc[rr][2], x0, w01.x); ffma2(acc[rr][3], x0, w01.y);
                ffma2(acc[rr][0], x1, w10.x); ffma2(acc[rr][1], x1, w10.y);
                ffma2(acc[rr][2], x1, w11.x); ffma2(acc[rr][3], x1, w11.y);
            }
        }
    }

    // reduce fh pairs: fh1 stores partials, fh0 adds
    __syncthreads();
    u64* red = (u64*)xs;                         // 128 threads x 16 u64 = 16KB
    int t128 = t & 127;
    if (fh == 1) {
#pragma unroll
        for (int rr = 0; rr < 4; rr++)
#pragma unroll
            for (int q = 0; q < 4; q++) red[t128 * 16 + rr * 4 + q] = acc[rr][q];
    }
    __syncthreads();
    if (fh == 0) {
        float4* out4 = (float4*)(g_part + chunk * NN * HH);
#pragma unroll
        for (int rr = 0; rr < 4; rr++) {
            int row = rowbase + rbase + rr * 32;
            if (row < NN) {
                u64 s0 = add2(acc[rr][0], red[t128 * 16 + rr * 4 + 0]);
                u64 s1 = add2(acc[rr][1], red[t128 * 16 + rr * 4 + 1]);
                u64 s2 = add2(acc[rr][2], red[t128 * 16 + rr * 4 + 2]);
                u64 s3 = add2(acc[rr][3], red[t128 * 16 + rr * 4 + 3]);
                float2 a = unpack2(s0); float2 b = unpack2(s1);
                float2 c = unpack2(s2); float2 d = unpack2(s3);
                out4[row * 4 + khalf * 2 + 0] = make_float4(a.x, a.y, b.x, b.y);
                out4[row * 4 + khalf * 2 + 1] = make_float4(c.x, c.y, d.x, d.y);
            }
        }
    }
}

// ---------------- gemm1 reduce: bufA = dinv * relu(sum parts + b) ----------
// also materializes g_dinv (from packed fixed-point degree) for k_agg.
__global__ __launch_bounds__(256) void k_gfin(const float* __restrict__ b) {
    int idx = blockIdx.x * 256 + threadIdx.x;      // float4 index
    if (idx >= NN * 4) return;
    const float4* p = (const float4*)g_part;
    float4 p0 = p[idx];
    float4 p1 = p[idx + NN * 4];
    float4 p2 = p[idx + NN * 8];
    float4 p3 = p[idx + NN * 12];
    int row = idx >> 2, k4 = idx & 3;
    float4 bb = __ldg(&((const float4*)b)[k4]);
    u64 pk = g_pack[row];
    float deg = 1.0f + (float)(pk & 0xFFFFFFFFFFull) * 5.9604645e-8f;
    float dv = rsqrtf(deg);
    if (k4 == 0) g_dinv[row] = dv;
    float4 o;
    o.x = fmaxf(p0.x + p1.x + p2.x + p3.x + bb.x, 0.f) * dv;
    o.y = fmaxf(p0.y + p1.y + p2.y + p3.y + bb.y, 0.f) * dv;
    o.z = fmaxf(p0.z + p1.z + p2.z + p3.z + bb.z, 0.f) * dv;
    o.w = fmaxf(p0.w + p1.w + p2.w + p3.w + bb.w, 0.f) * dv;
    ((float4*)g_bufA)[idx] = o;
}

// ---------------- fused conv: hout = [dinv*] relu((A @ hin) @ W + b) -------
// hin is pre-scaled by dinv (h' = dinv*h):
//   agg_c = dinv_c * ( sum_e ew_e * h'_r  +  h'_c )
// half-warp per node; 16-edge chunks read as 8x int4 (2 edges per LDG.128).
__global__ __launch_bounds__(256) void k_agg(const float* __restrict__ hin,
                                             float* __restrict__ hout,
                                             const float* __restrict__ W,
                                             const float* __restrict__ bias,
                                             int premul) {
    __shared__ float Ws[256];
    __shared__ float bs[16];
    __shared__ float hb[256];
    Ws[threadIdx.x] = W[threadIdx.x];
    if (threadIdx.x < 16) bs[threadIdx.x] = bias[threadIdx.x];
    __syncthreads();

    int tid = blockIdx.x * 256 + threadIdx.x;     // grid = NN*16/256 exactly
    int node = tid >> 4;
    int k = tid & 15;

    int cnt  = (int)(g_pack[node] >> 40);
    int base = node << 7;
    float acc = hin[node * 16 + k];               // self loop (already scaled)

    const int4* csr4 = (const int4*)g_csr;        // 2 edges per int4
    for (int e = 0; e < cnt; e += 16) {
#pragma unroll
        for (int j = 0; j < 8; j++) {
            int idx = e + j * 2;
            if (idx < cnt) {
                int4 pq = __ldg(&csr4[(base + idx) >> 1]);
                acc += __int_as_float(pq.y) * __ldg(&hin[pq.x * 16 + k]);
                if (idx + 1 < cnt)
                    acc += __int_as_float(pq.w) * __ldg(&hin[pq.z * 16 + k]);
            }
        }
    }
    float dv = g_dinv[node];
    acc *= dv;

    // 16x16 transform: exchange aggregated feats within the half-warp
    hb[threadIdx.x] = acc;
    __syncwarp();
    int hbase = threadIdx.x & ~15;
    float o = bs[k];
#pragma unroll
    for (int f = 0; f < 16; f++) o += hb[hbase + f] * Ws[f * 16 + k];
    float res = fmaxf(o, 0.0f);
    if (premul) res *= dv;                        // pre-scale for next layer
    hout[node * 16 + k] = res;
}

// ---------------- output: logits (16x40) + log_softmax --------------------
__global__ __launch_bounds__(256) void k_out(const float* __restrict__ Wo,
                                             const float* __restrict__ bo,
                                             float* __restrict__ out) {
    __shared__ float Ws[16 * 40];
    __shared__ float bs[40];
    for (int i = threadIdx.x; i < 640; i += 256) Ws[i] = Wo[i];
    if (threadIdx.x < 40) bs[threadIdx.x] = bo[threadIdx.x];
    __syncthreads();
    int idx = blockIdx.x * blockDim.x + threadIdx.x;
    if (idx >= NN) return;

    const float4* in4 = (const float4*)g_bufA;
    float hx[16];
#pragma unroll
    for (int q = 0; q < 4; q++) {
        float4 v = in4[idx * 4 + q];
        hx[q * 4 + 0] = v.x; hx[q * 4 + 1] = v.y;
        hx[q * 4 + 2] = v.z; hx[q * 4 + 3] = v.w;
    }
    float acc[40];
#pragma unroll
    for (int c = 0; c < 40; c++) acc[c] = bs[c];
#pragma unroll
    for (int f = 0; f < 16; f++) {
        float xv = hx[f];
#pragma unroll
        for (int c = 0; c < 40; c++) acc[c] += xv * Ws[f * 40 + c];
    }
    float m = acc[0];
#pragma unroll
    for (int c = 1; c < 40; c++) m = fmaxf(m, acc[c]);
    float s = 0.f;
#pragma unroll
    for (int c = 0; c < 40; c++) s += __expf(acc[c] - m);
    float lse = m + __logf(s);
#pragma unroll
    for (int c = 0; c < 40; c++) out[idx * 40 + c] = acc[c] - lse;
}

// ---------------- launch ---------------------------------------------------
extern "C" void kernel_launch(void* const* d_in, const int* in_sizes, int n_in,
                              void* d_out, int out_size) {
    const float* x  = (const float*)d_in[0];
    const int*   ei = (const int*)d_in[1];     // int32! (JAX x64 disabled)
    const float* ew = (const float*)d_in[2];
    const float* Wf = (const float*)d_in[3];
    const float* bf = (const float*)d_in[4];
    const float* W1 = (const float*)d_in[5];
    const float* b1 = (const float*)d_in[6];
    const float* W2 = (const float*)d_in[7];
    const float* b2 = (const float*)d_in[8];
    const float* Wo = (const float*)d_in[9];
    const float* bo = (const float*)d_in[10];
    float* out = (float*)d_out;

    float* bufA; float* bufB;
    cudaGetSymbolAddress((void**)&bufA, g_bufA);
    cudaGetSymbolAddress((void**)&bufB, g_bufB);

    k_init   <<<(NN + 255) / 256, 256>>>();
    k_fused  <<<FUSED_GRID, 256>>>(x, Wf, ei, ew);
    k_gfin   <<<(NN * 4 + 255) / 256, 256>>>(bf);

    k_agg    <<<NN * 16 / 256, 256>>>(bufA, bufB, W1, b1, 1);
    k_agg    <<<NN * 16 / 256, 256>>>(bufB, bufA, W2, b2, 0);

    k_out    <<<(NN + 255) / 256, 256>>>(Wo, bo, out);
}

// round 16
// speedup vs baseline: 1.5903x; 1.0847x over previous
#include <cuda_runtime.h>

#define NN 100000
#define EE 3200000
#define FIN 512
#define HH 16
#define CC 40
#define CAP 128            // bucket capacity per node (deg~Poisson(32), 17-sigma safe)
#define KCH 4              // gemm1 K-split chunks
#define RB  391            // row-blocks in gemm1 = ceil(NN/256)
#define SB  3125           // scatter blocks (EE / 1024)
#define FUSED_GRID 4692    // 1564 gemm (bi%3==0) + 3128 scatter slots

typedef unsigned long long u64;

// ---------------- scratch (device globals; no allocation allowed) ----------
__device__ u64   g_pack[NN];         // (slots<<40) | fixed24(sum ew)
__device__ float g_dinv[NN];
__device__ __align__(16) int2  g_csr[NN * CAP];     // {row, ew_bits}, bucketed
__device__ __align__(16) float g_part[KCH * NN * HH];
__device__ __align__(16) float g_bufA[NN * HH];
__device__ __align__(16) float g_bufB[NN * HH];

// ---------------- packed f32x2 helpers -------------------------------------
__device__ __forceinline__ void ffma2(u64& d, u64 a, u64 b) {
    asm("fma.rn.f32x2 %0, %1, %2, %0;" : "+l"(d) : "l"(a), "l"(b));
}
__device__ __forceinline__ u64 add2(u64 a, u64 b) {
    u64 r; asm("add.rn.f32x2 %0, %1, %2;" : "=l"(r) : "l"(a), "l"(b)); return r;
}
__device__ __forceinline__ u64 pack2(float a, float b) {
    u64 r; asm("mov.b64 %0, {%1, %2};" : "=l"(r) : "f"(a), "f"(b)); return r;
}
__device__ __forceinline__ float2 unpack2(u64 v) {
    float2 r; asm("mov.b64 {%0, %1}, %2;" : "=f"(r.x), "=f"(r.y) : "l"(v)); return r;
}

// ---------------- init: zero pack -------------------------------------------
__global__ void k_init() {
    int i = blockIdx.x * blockDim.x + threadIdx.x;
    if (i < NN) g_pack[i] = 0ull;
}

// ---------------- FUSED: scatter + gemm1 (independent work, one launch) ----
// bi%3==0  -> gemm1 block   (bid = bi/3, 0..1563)
// bi%3!=0  -> scatter block (sid = 2*(bi/3)+(bi%3)-1, 0..3127; >=SB idle)
__global__ __launch_bounds__(256) void k_fused(const float* __restrict__ x,
                                               const float* __restrict__ W,
                                               const int*   __restrict__ ei,
                                               const float* __restrict__ ew) {
    __shared__ float Ws[128 * 16];               // gemm W slice, 8 KB
    __shared__ __align__(16) float xs[256 * 18]; // gemm staging / reduce
    int bi = blockIdx.x;
    int t = threadIdx.x;

    if (bi % 3 != 0) {
        // ---------------- scatter body ----------------
        int sid = (bi / 3) * 2 + (bi % 3) - 1;
        if (sid >= SB) return;
        int e4 = (sid * 256 + t) * 4;
        int4   r = *(const int4*)(ei + e4);
        int4   c = *(const int4*)(ei + EE + e4);
        float4 w = *(const float4*)(ew + e4);
        u64 p, old;
        p = (1ull << 40) | (u64)__float2uint_rn(w.x * 16777216.0f);
        old = atomicAdd(&g_pack[c.x], p);
        g_csr[(c.x << 7) + (int)(old >> 40)] = make_int2(r.x, __float_as_int(w.x));
        p = (1ull << 40) | (u64)__float2uint_rn(w.y * 16777216.0f);
        old = atomicAdd(&g_pack[c.y], p);
        g_csr[(c.y << 7) + (int)(old >> 40)] = make_int2(r.y, __float_as_int(w.y));
        p = (1ull << 40) | (u64)__float2uint_rn(w.z * 16777216.0f);
        old = atomicAdd(&g_pack[c.z], p);
        g_csr[(c.z << 7) + (int)(old >> 40)] = make_int2(r.z, __float_as_int(w.z));
        p = (1ull << 40) | (u64)__float2uint_rn(w.w * 16777216.0f);
        old = atomicAdd(&g_pack[c.w], p);
        g_csr[(c.w << 7) + (int)(old >> 40)] = make_int2(r.w, __float_as_int(w.w));
        return;
    }

    // ---------------- gemm1 body (f-split warps, W in smem) ----------------
    int bid = bi / 3;
    int lane = t & 31;
    int w = t >> 5;
    int khalf = w & 1;
    int rg = (w >> 1) & 1;                       // row half (128 rows)
    int fh = w >> 2;                             // f half of tile
    int rbase = rg * 128 + lane;                 // local row of rr=0
    int rowblk = bid % RB;
    int chunk  = bid / RB;                       // K-chunk of 128 feats
    int rowbase = rowblk * 256;

    // stage W chunk slice once: 128 rows x 16 cols = 2048 floats
    {
        const float4* W4 = (const float4*)(W + chunk * 128 * 16);
        float4* Ws4 = (float4*)Ws;
        Ws4[t]       = W4[t];
        Ws4[t + 256] = W4[t + 256];
    }

    u64 acc[4][4];
#pragma unroll
    for (int rr = 0; rr < 4; rr++)
#pragma unroll
        for (int q = 0; q < 4; q++) acc[rr][q] = 0ull;

    const float4* x4 = (const float4*)x;

    for (int tile = 0; tile < 8; tile++) {       // 8 x 16 = 128 feats
        int fbase4 = chunk * 32 + tile * 4;      // in float4 units
        __syncthreads();
#pragma unroll
        for (int i = 0; i < 4; i++) {
            int idx = i * 256 + t;               // 0..1023 float4s
            int r = idx >> 2, f4 = idx & 3;
            int grow = rowbase + r;
            float4 v = make_float4(0.f, 0.f, 0.f, 0.f);
            if (grow < NN) v = x4[grow * (FIN / 4) + fbase4 + f4];
            float* dst = &xs[r * 18 + f4 * 4];
            *(float2*)(dst)     = make_float2(v.x, v.y);
            *(float2*)(dst + 2) = make_float2(v.z, v.w);
        }
        __syncthreads();
#pragma unroll
        for (int f2i = 0; f2i < 4; f2i++) {
            int f2 = fh * 4 + f2i;               // f-pair 0..7
            int fo = (tile * 16 + f2 * 2) * 16 + khalf * 8;
            ulonglong2 w00 = *(const ulonglong2*)(Ws + fo);       // f even
            ulonglong2 w01 = *(const ulonglong2*)(Ws + fo + 4);
            ulonglong2 w10 = *(const ulonglong2*)(Ws + fo + 16);  // f odd
            ulonglong2 w11 = *(const ulonglong2*)(Ws + fo + 20);
#pragma unroll
            for (int rr = 0; rr < 4; rr++) {
                float2 xv = *(const float2*)(xs + (rbase + rr * 32) * 18 + f2 * 2);
                u64 x0 = pack2(xv.x, xv.x);
                u64 x1 = pack2(xv.y, xv.y);
                ffma2(acc[rr][0], x0, w00.x); ffma2(acc[rr][1], x0, w00.y);
                ffma2(acc[rr][2], x0, w01.x); ffma2(acc[rr][3], x0, w01.y);
                ffma2(acc[rr][0], x1, w10.x); ffma2(acc[rr][1], x1, w10.y);
                ffma2(acc[rr][2], x1, w11.x); ffma2(acc[rr][3], x1, w11.y);
            }
        }
    }

    // reduce fh pairs: fh1 stores partials, fh0 adds
    __syncthreads();
    u64* red = (u64*)xs;                         // 128 threads x 16 u64 = 16KB
    int t128 = t & 127;
    if (fh == 1) {
#pragma unroll
        for (int rr = 0; rr < 4; rr++)
#pragma unroll
            for (int q = 0; q < 4; q++) red[t128 * 16 + rr * 4 + q] = acc[rr][q];
    }
    __syncthreads();
    if (fh == 0) {
        float4* out4 = (float4*)(g_part + chunk * NN * HH);
#pragma unroll
        for (int rr = 0; rr < 4; rr++) {
            int row = rowbase + rbase + rr * 32;
            if (row < NN) {
                u64 s0 = add2(acc[rr][0], red[t128 * 16 + rr * 4 + 0]);
                u64 s1 = add2(acc[rr][1], red[t128 * 16 + rr * 4 + 1]);
                u64 s2 = add2(acc[rr][2], red[t128 * 16 + rr * 4 + 2]);
                u64 s3 = add2(acc[rr][3], red[t128 * 16 + rr * 4 + 3]);
                float2 a = unpack2(s0); float2 b = unpack2(s1);
                float2 c = unpack2(s2); float2 d = unpack2(s3);
                out4[row * 4 + khalf * 2 + 0] = make_float4(a.x, a.y, b.x, b.y);
                out4[row * 4 + khalf * 2 + 1] = make_float4(c.x, c.y, d.x, d.y);
            }
        }
    }
}

// ---------------- gemm1 reduce + dinv + CSR zero-padding -------------------
// bufA = dinv * relu(sum parts + b); also pads each bucket to 16-multiple
// with {row=0, ew=0} entries so k_agg needs no bounds checks.
__global__ __launch_bounds__(256) void k_gfin(const float* __restrict__ b) {
    int idx = blockIdx.x * 256 + threadIdx.x;      // float4 index
    if (idx >= NN * 4) return;
    const float4* p = (const float4*)g_part;
    float4 p0 = p[idx];
    float4 p1 = p[idx + NN * 4];
    float4 p2 = p[idx + NN * 8];
    float4 p3 = p[idx + NN * 12];
    int row = idx >> 2, k4 = idx & 3;
    float4 bb = __ldg(&((const float4*)b)[k4]);
    u64 pk = g_pack[row];
    float deg = 1.0f + (float)(pk & 0xFFFFFFFFFFull) * 5.9604645e-8f;
    float dv = rsqrtf(deg);
    if (k4 == 0) g_dinv[row] = dv;
    float4 o;
    o.x = fmaxf(p0.x + p1.x + p2.x + p3.x + bb.x, 0.f) * dv;
    o.y = fmaxf(p0.y + p1.y + p2.y + p3.y + bb.y, 0.f) * dv;
    o.z = fmaxf(p0.z + p1.z + p2.z + p3.z + bb.z, 0.f) * dv;
    o.w = fmaxf(p0.w + p1.w + p2.w + p3.w + bb.w, 0.f) * dv;
    ((float4*)g_bufA)[idx] = o;

    // zero-pad bucket [cnt, cnt16): 4 threads stride the <=15 pad slots
    int cnt = (int)(pk >> 40);
    int cnt16 = (cnt + 15) & ~15;
    int2* bucket = g_csr + (row << 7);
#pragma unroll
    for (int j = 0; j < 4; j++) {
        int s = cnt + k4 + j * 4;
        if (s < cnt16) bucket[s] = make_int2(0, 0);
    }
}

// ---------------- fused conv: hout = [dinv*] relu((A @ hin) @ W + b) -------
// hin pre-scaled by dinv; buckets zero-padded to 16 -> branch-free loop.
// half-warp per node; dual accumulators break the FFMA chain.
__global__ __launch_bounds__(256) void k_agg(const float* __restrict__ hin,
                                             float* __restrict__ hout,
                                             const float* __restrict__ W,
                                             const float* __restrict__ bias,
                                             int premul) {
    __shared__ float Ws[256];
    __shared__ float bs[16];
    __shared__ float hb[256];
    Ws[threadIdx.x] = W[threadIdx.x];
    if (threadIdx.x < 16) bs[threadIdx.x] = bias[threadIdx.x];
    __syncthreads();

    int tid = blockIdx.x * 256 + threadIdx.x;     // grid = NN*16/256 exactly
    int node = tid >> 4;
    int k = tid & 15;

    int cnt16 = ((int)(g_pack[node] >> 40) + 15) & ~15;
    float acc0 = hin[node * 16 + k];              // self loop (already scaled)
    float acc1 = 0.f;

    const int4* bp = (const int4*)(g_csr + (node << 7));  // 2 edges per int4
    for (int e = 0; e < cnt16; e += 16) {
        const int4* cp = bp + (e >> 1);
#pragma unroll
        for (int j = 0; j < 8; j++) {
            int4 pq = __ldg(&cp[j]);
            acc0 += __int_as_float(pq.y) * __ldg(&hin[pq.x * 16 + k]);
            acc1 += __int_as_float(pq.w) * __ldg(&hin[pq.z * 16 + k]);
        }
    }
    float dv = g_dinv[node];
    float acc = (acc0 + acc1) * dv;

    // 16x16 transform: exchange aggregated feats within the half-warp
    hb[threadIdx.x] = acc;
    __syncwarp();
    int hbase = threadIdx.x & ~15;
    float o = bs[k];
#pragma unroll
    for (int f = 0; f < 16; f++) o += hb[hbase + f] * Ws[f * 16 + k];
    float res = fmaxf(o, 0.0f);
    if (premul) res *= dv;                        // pre-scale for next layer
    hout[node * 16 + k] = res;
}

// ---------------- output: logits (16x40) + log_softmax --------------------
__global__ __launch_bounds__(256) void k_out(const float* __restrict__ Wo,
                                             const float* __restrict__ bo,
                                             float* __restrict__ out) {
    __shared__ float Ws[16 * 40];
    __shared__ float bs[40];
    for (int i = threadIdx.x; i < 640; i += 256) Ws[i] = Wo[i];
    if (threadIdx.x < 40) bs[threadIdx.x] = bo[threadIdx.x];
    __syncthreads();
    int idx = blockIdx.x * blockDim.x + threadIdx.x;
    if (idx >= NN) return;

    const float4* in4 = (const float4*)g_bufA;
    float hx[16];
#pragma unroll
    for (int q = 0; q < 4; q++) {
        float4 v = in4[idx * 4 + q];
        hx[q * 4 + 0] = v.x; hx[q * 4 + 1] = v.y;
        hx[q * 4 + 2] = v.z; hx[q * 4 + 3] = v.w;
    }
    float acc[40];
#pragma unroll
    for (int c = 0; c < 40; c++) acc[c] = bs[c];
#pragma unroll
    for (int f = 0; f < 16; f++) {
        float xv = hx[f];
#pragma unroll
        for (int c = 0; c < 40; c++) acc[c] += xv * Ws[f * 40 + c];
    }
    float m = acc[0];
#pragma unroll
    for (int c = 1; c < 40; c++) m = fmaxf(m, acc[c]);
    float s = 0.f;
#pragma unroll
    for (int c = 0; c < 40; c++) s += __expf(acc[c] - m);
    float lse = m + __logf(s);
#pragma unroll
    for (int c = 0; c < 40; c++) out[idx * 40 + c] = acc[c] - lse;
}

// ---------------- launch ---------------------------------------------------
extern "C" void kernel_launch(void* const* d_in, const int* in_sizes, int n_in,
                              void* d_out, int out_size) {
    const float* x  = (const float*)d_in[0];
    const int*   ei = (const int*)d_in[1];     // int32! (JAX x64 disabled)
    const float* ew = (const float*)d_in[2];
    const float* Wf = (const float*)d_in[3];
    const float* bf = (const float*)d_in[4];
    const float* W1 = (const float*)d_in[5];
    const float* b1 = (const float*)d_in[6];
    const float* W2 = (const float*)d_in[7];
    const float* b2 = (const float*)d_in[8];
    const float* Wo = (const float*)d_in[9];
    const float* bo = (const float*)d_in[10];
    float* out = (float*)d_out;

    float* bufA; float* bufB;
    cudaGetSymbolAddress((void**)&bufA, g_bufA);
    cudaGetSymbolAddress((void**)&bufB, g_bufB);

    k_init   <<<(NN + 255) / 256, 256>>>();
    k_fused  <<<FUSED_GRID, 256>>>(x, Wf, ei, ew);
    k_gfin   <<<(NN * 4 + 255) / 256, 256>>>(bf);

    k_agg    <<<NN * 16 / 256, 256>>>(bufA, bufB, W1, b1, 1);
    k_agg    <<<NN * 16 / 256, 256>>>(bufB, bufA, W2, b2, 0);

    k_out    <<<(NN + 255) / 256, 256>>>(Wo, bo, out);
}